// round 11
// baseline (speedup 1.0000x reference)
#include <cuda_runtime.h>
#include <cstdint>

// ---------------------------------------------------------------------------
// Problem constants
// ---------------------------------------------------------------------------
#define B_      4
#define N_      2048
#define D_      512
#define H_      8
#define DH_     64
#define ROWS_   (B_ * N_)          // 8192
#define W3_     1536
#define SCALE_  0.125f             // 64^-0.5
#define LOG2E_  1.4426950408889634f
#define KEXP_   (SCALE_ * LOG2E_)  // multiply logits once, feed exp2f
#define NT_     (N_ / 64)          // 32 j-tiles

// ---------------------------------------------------------------------------
// Scratch: 16 MB KV buffer (reused across two half-batch rounds) + LN stats.
// K stored transposed:  K_T[bb][h][d][n]   at offset 0        (8 MB)
// V stored natural:     V  [bb][h][n][d]   at offset VOFF_    (8 MB)
// ---------------------------------------------------------------------------
#define VOFF_   (2 * H_ * DH_ * N_)            // 2097152 floats
__device__ float g_kv[2 * VOFF_];              // 16 MB
__device__ float g_mu[ROWS_];
__device__ float g_rstd[ROWS_];

// ---------------------------------------------------------------------------
// f32x2 packed-FMA helpers (FFMA2: full-rate fp32 on Blackwell)
// ---------------------------------------------------------------------------
__device__ __forceinline__ unsigned long long bcast2(float v) {
    unsigned long long r;
    unsigned int x = __float_as_uint(v);
    asm("mov.b64 %0, {%1, %2};" : "=l"(r) : "r"(x), "r"(x));
    return r;
}
__device__ __forceinline__ void ffma2(unsigned long long& d,
                                      unsigned long long a,
                                      unsigned long long b) {
    asm("fma.rn.f32x2 %0, %1, %2, %0;" : "+l"(d) : "l"(a), "l"(b));
}
union F2U { unsigned long long u; float2 f; };

// cp.async 16B helpers
__device__ __forceinline__ void cp16(uint32_t dst, const float* src) {
    asm volatile("cp.async.cg.shared.global [%0], [%1], 16;"
                 :: "r"(dst), "l"(src));
}
__device__ __forceinline__ void cp_commit() {
    asm volatile("cp.async.commit_group;");
}
__device__ __forceinline__ void cp_wait0() {
    asm volatile("cp.async.wait_group 0;" ::: "memory");
}

// ---------------------------------------------------------------------------
// Kernel A: zero d_out (poisoned; attention accumulates atomically).
// ---------------------------------------------------------------------------
__global__ void __launch_bounds__(256, 1) zero_out_kernel(float4* o) {
    o[blockIdx.x * 256 + threadIdx.x] = make_float4(0.f, 0.f, 0.f, 0.f);
}

// ---------------------------------------------------------------------------
// Kernel B: per-row LayerNorm stats. One 128-thread block per row.
// ---------------------------------------------------------------------------
__global__ void __launch_bounds__(128, 1)
ln_stats_kernel(const float* __restrict__ x) {
    int row = blockIdx.x;
    float4 v = reinterpret_cast<const float4*>(x + (size_t)row * D_)[threadIdx.x];
    float s  = v.x + v.y + v.z + v.w;
    float s2 = v.x * v.x + v.y * v.y + v.z * v.z + v.w * v.w;
    #pragma unroll
    for (int off = 16; off > 0; off >>= 1) {
        s  += __shfl_xor_sync(0xffffffffu, s,  off);
        s2 += __shfl_xor_sync(0xffffffffu, s2, off);
    }
    __shared__ float sh[8];
    int w = threadIdx.x >> 5;
    if ((threadIdx.x & 31) == 0) { sh[w] = s; sh[w + 4] = s2; }
    __syncthreads();
    if (threadIdx.x == 0) {
        s  = sh[0] + sh[1] + sh[2] + sh[3];
        s2 = sh[4] + sh[5] + sh[6] + sh[7];
        float mu  = s * (1.0f / D_);
        float var = s2 * (1.0f / D_) - mu * mu;
        g_mu[row]   = mu;
        g_rstd[row] = rsqrtf(var + 1e-5f);
    }
}

// ---------------------------------------------------------------------------
// Kernel C: KV projection (unchanged — proven correct, ~13% of runtime).
// ---------------------------------------------------------------------------
#define BM 128
#define BN 128
#define BK 16

__global__ void __launch_bounds__(256, 1)
kvproj_kernel(const float* __restrict__ x,
              const float* __restrict__ gamma,
              const float* __restrict__ beta,
              const float* __restrict__ W,
              int half) {
    __shared__ float As[BK][BM];
    __shared__ float Bs[BK][BN];
    int tid = threadIdx.x;
    int tx = tid & 15, ty = tid >> 4;
    int m0 = half * (2 * N_) + blockIdx.y * BM;
    int n0 = D_ + blockIdx.x * BN;

    float acc[8][8];
    #pragma unroll
    for (int i = 0; i < 8; i++)
        #pragma unroll
        for (int j = 0; j < 8; j++) acc[i][j] = 0.f;

    for (int kt = 0; kt < D_; kt += BK) {
        #pragma unroll
        for (int i = 0; i < 8; i++) {
            int e = tid + i * 256;
            int m = e >> 4, kk = e & 15;
            int row = m0 + m;
            float xv = x[(size_t)row * D_ + kt + kk];
            xv = (xv - g_mu[row]) * g_rstd[row] * gamma[kt + kk] + beta[kt + kk];
            As[kk][m] = xv;
        }
        #pragma unroll
        for (int i = 0; i < 8; i++) {
            int e = tid + i * 256;
            int kk = e >> 7, n = e & 127;
            Bs[kk][n] = W[(size_t)(kt + kk) * W3_ + n0 + n];
        }
        __syncthreads();
        #pragma unroll
        for (int k = 0; k < BK; k++) {
            float4 a0 = *(const float4*)&As[k][ty * 8];
            float4 a1 = *(const float4*)&As[k][ty * 8 + 4];
            float4 b0 = *(const float4*)&Bs[k][tx * 8];
            float4 b1 = *(const float4*)&Bs[k][tx * 8 + 4];
            float av[8] = {a0.x, a0.y, a0.z, a0.w, a1.x, a1.y, a1.z, a1.w};
            float bv[8] = {b0.x, b0.y, b0.z, b0.w, b1.x, b1.y, b1.z, b1.w};
            #pragma unroll
            for (int i = 0; i < 8; i++)
                #pragma unroll
                for (int j = 0; j < 8; j++)
                    acc[i][j] = fmaf(av[i], bv[j], acc[i][j]);
        }
        __syncthreads();
    }

    int col_rel = (n0 - D_) + tx * 8;
    int kvsel   = col_rel >> 9;
    int within  = col_rel & 511;
    int h  = within >> 6;
    int d0 = within & 63;
    #pragma unroll
    for (int i = 0; i < 8; i++) {
        int r  = m0 + ty * 8 + i;
        int bb = (r >> 11) & 1;
        int n  = r & (N_ - 1);
        if (kvsel == 0) {
            size_t base = ((size_t)((bb * H_ + h) * DH_ + d0)) * N_ + n;
            #pragma unroll
            for (int jj = 0; jj < 8; jj++)
                g_kv[base + (size_t)jj * N_] = acc[i][jj];
        } else {
            size_t base = VOFF_ + ((size_t)((bb * H_ + h) * N_ + n)) * DH_ + d0;
            *(float4*)&g_kv[base] =
                make_float4(acc[i][0], acc[i][1], acc[i][2], acc[i][3]);
            *(float4*)&g_kv[base + 4] =
                make_float4(acc[i][4], acc[i][5], acc[i][6], acc[i][7]);
        }
    }
}

// ---------------------------------------------------------------------------
// Kernel D: fused Q-proj + flash attention (no-max softmax, deferred l)
//           + out-proj, with cp.async double-buffered K/V pipeline.
// smem regions (floats):
//   smQ   @0      Qs[d][i]
//   smK0  @4096   K buf0   (also W staging in Q-proj epilogue / out-proj)
//   smK1  @8192   K buf1   (also W staging in Q-proj)
//   smV0  @12288  V buf0
//   smV1  @16384  V buf1
//   smP   @20480  P[i][j]  (also xs staging in Q-proj; ao in epilogue)
// 96 KB dynamic smem, 2 CTAs/SM.
// ---------------------------------------------------------------------------
#define ATTN_SMEM (24576 * 4)      // 98304 B

__global__ void __launch_bounds__(256, 2)
attn_kernel(const float* __restrict__ x,
            const float* __restrict__ gamma,
            const float* __restrict__ beta,
            const float* __restrict__ w_qkv,
            const float* __restrict__ w_out,
            float* __restrict__ out,
            int half) {
    extern __shared__ float sm[];
    float* smQ = sm;
    float* smP = sm + 20480;
    uint32_t smb = (uint32_t)__cvta_generic_to_shared(sm);

    int tid = threadIdx.x;
    int tx = tid & 15, ty = tid >> 4;
    int bb = blockIdx.y >> 3;
    int h  = blockIdx.y & 7;
    int b  = half * 2 + bb;
    int i0 = blockIdx.x * 64;

    // ---- Q projection: Q = LN(x)[64 rows] @ Wq[:, h*64..+63], FFMA2 ----
    // xs staging in smP (pitch 68), W staging in smK1 (sm+8192).
    float* xs = smP;
    float* Ws = sm + 8192;
    unsigned long long qa2[4][2];
    #pragma unroll
    for (int i = 0; i < 4; i++) { qa2[i][0] = 0ull; qa2[i][1] = 0ull; }

    for (int kt = 0; kt < D_; kt += 32) {
        #pragma unroll
        for (int it = 0; it < 8; it++) {
            int e = tid + it * 256;
            int i = e >> 5, k = e & 31;
            int row = b * N_ + i0 + i;
            float xv = x[(size_t)row * D_ + kt + k];
            xv = (xv - g_mu[row]) * g_rstd[row] * gamma[kt + k] + beta[kt + k];
            xs[k * 68 + i] = xv;
        }
        #pragma unroll
        for (int it = 0; it < 8; it++) {
            int e = tid + it * 256;
            int d = e & 63, k = e >> 6;
            Ws[k * 64 + d] = w_qkv[(size_t)(kt + k) * W3_ + h * DH_ + d];
        }
        __syncthreads();
        #pragma unroll
        for (int k = 0; k < 32; k++) {
            float4 aq = *(const float4*)&xs[k * 68 + ty * 4];
            ulonglong2 bw = *(const ulonglong2*)&Ws[k * 64 + tx * 4];
            unsigned long long a0 = bcast2(aq.x), a1 = bcast2(aq.y);
            unsigned long long a2 = bcast2(aq.z), a3 = bcast2(aq.w);
            ffma2(qa2[0][0], a0, bw.x); ffma2(qa2[0][1], a0, bw.y);
            ffma2(qa2[1][0], a1, bw.x); ffma2(qa2[1][1], a1, bw.y);
            ffma2(qa2[2][0], a2, bw.x); ffma2(qa2[2][1], a2, bw.y);
            ffma2(qa2[3][0], a3, bw.x); ffma2(qa2[3][1], a3, bw.y);
        }
        __syncthreads();
    }
    // smQ[d][i]; pair jp covers d = tx*4+2jp, +1
    #pragma unroll
    for (int i = 0; i < 4; i++) {
        #pragma unroll
        for (int jp = 0; jp < 2; jp++) {
            F2U u; u.u = qa2[i][jp];
            smQ[(tx * 4 + 2 * jp) * 64 + ty * 4 + i]     = u.f.x;
            smQ[(tx * 4 + 2 * jp + 1) * 64 + ty * 4 + i] = u.f.y;
        }
    }

    // ---- flash attention (no-max softmax) over j-tiles ----
    const float* gK = g_kv + ((size_t)(bb * H_ + h) * DH_) * N_;          // [d][n]
    const float* gV = g_kv + VOFF_ + ((size_t)(bb * H_ + h) * N_) * DH_;  // [n][d]

    float lp[4] = {0.f, 0.f, 0.f, 0.f};   // per-thread partial l (own 4 j's)
    unsigned long long o2[4][2];
    #pragma unroll
    for (int i = 0; i < 4; i++) { o2[i][0] = 0ull; o2[i][1] = 0ull; }

    int ldj4 = (tid & 15) * 4;
    int ldk  = tid >> 4;

    // prologue: async-load tile 0 into buf0
    {
        uint32_t kb = smb + (4096u) * 4;
        uint32_t vb = smb + (12288u) * 4;
        #pragma unroll
        for (int p = 0; p < 4; p++) {
            int d = ldk + p * 16;
            cp16(kb + (uint32_t)(d * 64 + ldj4) * 4, &gK[(size_t)d * N_ + ldj4]);
        }
        #pragma unroll
        for (int p = 0; p < 4; p++) {
            int j = ldk + p * 16;
            cp16(vb + (uint32_t)(j * 64 + ldj4) * 4, &gV[(size_t)j * DH_ + ldj4]);
        }
        cp_commit();
    }

    for (int t = 0; t < NT_; t++) {
        cp_wait0();
        __syncthreads();   // tile t resident everywhere; smP free (PV t-1 done)

        if (t + 1 < NT_) {
            int j0n = (t + 1) * 64;
            uint32_t kb = smb + (4096u + (uint32_t)((t + 1) & 1) * 4096u) * 4;
            uint32_t vb = smb + (12288u + (uint32_t)((t + 1) & 1) * 4096u) * 4;
            #pragma unroll
            for (int p = 0; p < 4; p++) {
                int d = ldk + p * 16;
                cp16(kb + (uint32_t)(d * 64 + ldj4) * 4,
                     &gK[(size_t)d * N_ + j0n + ldj4]);
            }
            #pragma unroll
            for (int p = 0; p < 4; p++) {
                int j = ldk + p * 16;
                cp16(vb + (uint32_t)(j * 64 + ldj4) * 4,
                     &gV[(size_t)(j0n + j) * DH_ + ldj4]);
            }
            cp_commit();
        }

        const float* Ks = sm + 4096 + (t & 1) * 4096;
        const float* Vs = sm + 12288 + (t & 1) * 4096;

        // S = Q K^T, packed over j
        unsigned long long s2[4][2];
        #pragma unroll
        for (int i = 0; i < 4; i++) { s2[i][0] = 0ull; s2[i][1] = 0ull; }
        #pragma unroll 8
        for (int d = 0; d < 64; d++) {
            float4 aq = *(const float4*)&smQ[d * 64 + ty * 4];
            ulonglong2 bk = *(const ulonglong2*)&Ks[d * 64 + tx * 4];
            unsigned long long a0 = bcast2(aq.x), a1 = bcast2(aq.y);
            unsigned long long a2 = bcast2(aq.z), a3 = bcast2(aq.w);
            ffma2(s2[0][0], a0, bk.x); ffma2(s2[0][1], a0, bk.y);
            ffma2(s2[1][0], a1, bk.x); ffma2(s2[1][1], a1, bk.y);
            ffma2(s2[2][0], a2, bk.x); ffma2(s2[2][1], a2, bk.y);
            ffma2(s2[3][0], a3, bk.x); ffma2(s2[3][1], a3, bk.y);
        }

        // exp (no max subtraction), accumulate partial l, stage P
        #pragma unroll
        for (int i = 0; i < 4; i++) {
            F2U u0, u1; u0.u = s2[i][0]; u1.u = s2[i][1];
            float p0 = exp2f(u0.f.x * KEXP_);
            float p1 = exp2f(u0.f.y * KEXP_);
            float p2 = exp2f(u1.f.x * KEXP_);
            float p3 = exp2f(u1.f.y * KEXP_);
            lp[i] += (p0 + p1) + (p2 + p3);
            *(float4*)&smP[(ty * 4 + i) * 64 + tx * 4] =
                make_float4(p0, p1, p2, p3);
        }
        __syncthreads();   // P visible

        // O += P V, packed over d
        #pragma unroll 4
        for (int j4 = 0; j4 < 64; j4 += 4) {
            float4 pr0 = *(const float4*)&smP[(ty * 4 + 0) * 64 + j4];
            float4 pr1 = *(const float4*)&smP[(ty * 4 + 1) * 64 + j4];
            float4 pr2 = *(const float4*)&smP[(ty * 4 + 2) * 64 + j4];
            float4 pr3 = *(const float4*)&smP[(ty * 4 + 3) * 64 + j4];
            #pragma unroll
            for (int jj = 0; jj < 4; jj++) {
                ulonglong2 vv = *(const ulonglong2*)&Vs[(j4 + jj) * 64 + tx * 4];
                float pj0 = (jj == 0) ? pr0.x : (jj == 1) ? pr0.y : (jj == 2) ? pr0.z : pr0.w;
                float pj1 = (jj == 0) ? pr1.x : (jj == 1) ? pr1.y : (jj == 2) ? pr1.z : pr1.w;
                float pj2 = (jj == 0) ? pr2.x : (jj == 1) ? pr2.y : (jj == 2) ? pr2.z : pr2.w;
                float pj3 = (jj == 0) ? pr3.x : (jj == 1) ? pr3.y : (jj == 2) ? pr3.z : pr3.w;
                unsigned long long b0 = bcast2(pj0), b1 = bcast2(pj1);
                unsigned long long b2 = bcast2(pj2), b3 = bcast2(pj3);
                ffma2(o2[0][0], b0, vv.x); ffma2(o2[0][1], b0, vv.y);
                ffma2(o2[1][0], b1, vv.x); ffma2(o2[1][1], b1, vv.y);
                ffma2(o2[2][0], b2, vv.x); ffma2(o2[2][1], b2, vv.y);
                ffma2(o2[3][0], b3, vv.x); ffma2(o2[3][1], b3, vv.y);
            }
        }
    }

    // ---- finalize l (one shuffle reduce over the 16-lane ty group) ----
    #pragma unroll
    for (int i = 0; i < 4; i++) {
        #pragma unroll
        for (int off = 8; off > 0; off >>= 1)
            lp[i] += __shfl_xor_sync(0xffffffffu, lp[i], off);
    }

    // ao -> smP rows are ty-private (written & read only by same half-warp)
    __syncwarp();
    #pragma unroll
    for (int i = 0; i < 4; i++) {
        float inv = 1.0f / lp[i];
        F2U u0, u1; u0.u = o2[i][0]; u1.u = o2[i][1];
        *(float4*)&smP[(ty * 4 + i) * 64 + tx * 4] =
            make_float4(u0.f.x * inv, u0.f.y * inv,
                        u1.f.x * inv, u1.f.y * inv);
    }

    // ---- out-projection: out += ao @ Wout[h*64..+63, :], FFMA2 ----
    float* Wo = sm + 4096;   // reuse K buf0
    for (int nt = 0; nt < D_; nt += 64) {
        __syncthreads();   // all warps done with prior use of Wo
        #pragma unroll
        for (int it = 0; it < 4; it++) {
            int e = tid + it * 256;
            int n4 = (e & 15) * 4, d = e >> 4;
            *(float4*)&Wo[d * 64 + n4] =
                *(const float4*)&w_out[(size_t)(h * DH_ + d) * D_ + nt + n4];
        }
        __syncthreads();
        unsigned long long c2[4][2];
        #pragma unroll
        for (int i = 0; i < 4; i++) { c2[i][0] = 0ull; c2[i][1] = 0ull; }
        #pragma unroll 8
        for (int d = 0; d < 64; d++) {
            ulonglong2 ww = *(const ulonglong2*)&Wo[d * 64 + tx * 4];
            unsigned long long a0 = bcast2(smP[(ty * 4 + 0) * 64 + d]);
            unsigned long long a1 = bcast2(smP[(ty * 4 + 1) * 64 + d]);
            unsigned long long a2 = bcast2(smP[(ty * 4 + 2) * 64 + d]);
            unsigned long long a3 = bcast2(smP[(ty * 4 + 3) * 64 + d]);
            ffma2(c2[0][0], a0, ww.x); ffma2(c2[0][1], a0, ww.y);
            ffma2(c2[1][0], a1, ww.x); ffma2(c2[1][1], a1, ww.y);
            ffma2(c2[2][0], a2, ww.x); ffma2(c2[2][1], a2, ww.y);
            ffma2(c2[3][0], a3, ww.x); ffma2(c2[3][1], a3, ww.y);
        }
        #pragma unroll
        for (int i = 0; i < 4; i++) {
            size_t rbase = (size_t)(b * N_ + i0 + ty * 4 + i) * D_ + nt + tx * 4;
            #pragma unroll
            for (int jp = 0; jp < 2; jp++) {
                F2U u; u.u = c2[i][jp];
                atomicAdd(&out[rbase + 2 * jp],     u.f.x);
                atomicAdd(&out[rbase + 2 * jp + 1], u.f.y);
            }
        }
    }
}

// ---------------------------------------------------------------------------
// Launch: zero -> LN stats -> 2x (KV-proj -> fused attention)
// ---------------------------------------------------------------------------
extern "C" void kernel_launch(void* const* d_in, const int* in_sizes, int n_in,
                              void* d_out, int out_size) {
    const float* x     = (const float*)d_in[0];
    const float* gamma = (const float*)d_in[1];
    const float* beta  = (const float*)d_in[2];
    const float* w_qkv = (const float*)d_in[3];
    const float* w_out = (const float*)d_in[4];
    float* out = (float*)d_out;
    (void)in_sizes; (void)n_in; (void)out_size;

    cudaFuncSetAttribute(attn_kernel,
                         cudaFuncAttributeMaxDynamicSharedMemorySize,
                         ATTN_SMEM);

    zero_out_kernel<<<ROWS_ * D_ / 1024, 256>>>((float4*)out);
    ln_stats_kernel<<<ROWS_, 128>>>(x);

    for (int half = 0; half < 2; half++) {
        kvproj_kernel<<<dim3(2 * D_ / BN, 2 * N_ / BM), 256>>>(
            x, gamma, beta, w_qkv, half);
        attn_kernel<<<dim3(N_ / 64, 2 * H_), 256, ATTN_SMEM>>>(
            x, gamma, beta, w_qkv, w_out, out, half);
    }
}

// round 12
// speedup vs baseline: 1.0869x; 1.0869x over previous
#include <cuda_runtime.h>
#include <cstdint>

#define B_      4
#define N_      2048
#define D_      512
#define H_      8
#define DH_     64
#define ROWS_   (B_ * N_)
#define W3_     1536
#define KEXP_   0.18033688011112042f   // 64^-0.5 * log2(e)
#define NT_     (N_ / 64)

#define VOFF_   (2 * H_ * DH_ * N_)
__device__ float g_kv[2 * VOFF_];
__device__ float g_mu[ROWS_];
__device__ float g_rstd[ROWS_];

__device__ __forceinline__ unsigned long long bcast2(float v) {
    unsigned long long r; unsigned int x = __float_as_uint(v);
    asm("mov.b64 %0, {%1, %2};" : "=l"(r) : "r"(x), "r"(x));
    return r;
}
__device__ __forceinline__ void ffma2(unsigned long long& d,
                                      unsigned long long a,
                                      unsigned long long b) {
    asm("fma.rn.f32x2 %0, %1, %2, %0;" : "+l"(d) : "l"(a), "l"(b));
}
union F2U { unsigned long long u; float2 f; };

__device__ __forceinline__ void cp16(uint32_t dst, const float* src) {
    asm volatile("cp.async.cg.shared.global [%0], [%1], 16;" :: "r"(dst), "l"(src));
}
__device__ __forceinline__ void cp_commit() {
    asm volatile("cp.async.commit_group;");
}
template <int NN>
__device__ __forceinline__ void cp_wait() {
    asm volatile("cp.async.wait_group %0;" :: "n"(NN) : "memory");
}

__global__ void __launch_bounds__(256, 1) zero_out_kernel(float4* o) {
    o[blockIdx.x * 256 + threadIdx.x] = make_float4(0.f, 0.f, 0.f, 0.f);
}

__global__ void __launch_bounds__(128, 1)
ln_stats_kernel(const float* __restrict__ x) {
    int row = blockIdx.x;
    float4 v = reinterpret_cast<const float4*>(x + (size_t)row * D_)[threadIdx.x];
    float s  = v.x + v.y + v.z + v.w;
    float s2 = v.x * v.x + v.y * v.y + v.z * v.z + v.w * v.w;
    #pragma unroll
    for (int off = 16; off > 0; off >>= 1) {
        s  += __shfl_xor_sync(0xffffffffu, s,  off);
        s2 += __shfl_xor_sync(0xffffffffu, s2, off);
    }
    __shared__ float sh[8];
    int w = threadIdx.x >> 5;
    if ((threadIdx.x & 31) == 0) { sh[w] = s; sh[w + 4] = s2; }
    __syncthreads();
    if (threadIdx.x == 0) {
        s  = sh[0] + sh[1] + sh[2] + sh[3];
        s2 = sh[4] + sh[5] + sh[6] + sh[7];
        float mu  = s * (1.0f / D_);
        float var = s2 * (1.0f / D_) - mu * mu;
        g_mu[row] = mu; g_rstd[row] = rsqrtf(var + 1e-5f);
    }
}

// --------------------------- KV projection (unchanged) ---------------------
#define BM 128
#define BN 128
#define BK 16

__global__ void __launch_bounds__(256, 1)
kvproj_kernel(const float* __restrict__ x, const float* __restrict__ gamma,
              const float* __restrict__ beta, const float* __restrict__ W,
              int half) {
    __shared__ float As[BK][BM];
    __shared__ float Bs[BK][BN];
    int tid = threadIdx.x;
    int tx = tid & 15, ty = tid >> 4;
    int m0 = half * (2 * N_) + blockIdx.y * BM;
    int n0 = D_ + blockIdx.x * BN;

    float acc[8][8];
    #pragma unroll
    for (int i = 0; i < 8; i++)
        #pragma unroll
        for (int j = 0; j < 8; j++) acc[i][j] = 0.f;

    for (int kt = 0; kt < D_; kt += BK) {
        #pragma unroll
        for (int i = 0; i < 8; i++) {
            int e = tid + i * 256;
            int m = e >> 4, kk = e & 15;
            int row = m0 + m;
            float xv = x[(size_t)row * D_ + kt + kk];
            xv = (xv - g_mu[row]) * g_rstd[row] * gamma[kt + kk] + beta[kt + kk];
            As[kk][m] = xv;
        }
        #pragma unroll
        for (int i = 0; i < 8; i++) {
            int e = tid + i * 256;
            int kk = e >> 7, n = e & 127;
            Bs[kk][n] = W[(size_t)(kt + kk) * W3_ + n0 + n];
        }
        __syncthreads();
        #pragma unroll
        for (int k = 0; k < BK; k++) {
            float4 a0 = *(const float4*)&As[k][ty * 8];
            float4 a1 = *(const float4*)&As[k][ty * 8 + 4];
            float4 b0 = *(const float4*)&Bs[k][tx * 8];
            float4 b1 = *(const float4*)&Bs[k][tx * 8 + 4];
            float av[8] = {a0.x, a0.y, a0.z, a0.w, a1.x, a1.y, a1.z, a1.w};
            float bv[8] = {b0.x, b0.y, b0.z, b0.w, b1.x, b1.y, b1.z, b1.w};
            #pragma unroll
            for (int i = 0; i < 8; i++)
                #pragma unroll
                for (int j = 0; j < 8; j++)
                    acc[i][j] = fmaf(av[i], bv[j], acc[i][j]);
        }
        __syncthreads();
    }

    int col_rel = (n0 - D_) + tx * 8;
    int kvsel = col_rel >> 9, within = col_rel & 511;
    int h = within >> 6, d0 = within & 63;
    #pragma unroll
    for (int i = 0; i < 8; i++) {
        int r = m0 + ty * 8 + i;
        int bb = (r >> 11) & 1, n = r & (N_ - 1);
        if (kvsel == 0) {
            size_t base = ((size_t)((bb * H_ + h) * DH_ + d0)) * N_ + n;
            #pragma unroll
            for (int jj = 0; jj < 8; jj++)
                g_kv[base + (size_t)jj * N_] = acc[i][jj];
        } else {
            size_t base = VOFF_ + ((size_t)((bb * H_ + h) * N_ + n)) * DH_ + d0;
            *(float4*)&g_kv[base] =
                make_float4(acc[i][0], acc[i][1], acc[i][2], acc[i][3]);
            *(float4*)&g_kv[base + 4] =
                make_float4(acc[i][4], acc[i][5], acc[i][6], acc[i][7]);
        }
    }
}

// ---------------------------------------------------------------------------
// Kernel D: fused Q-proj + attention + out-proj. 128 q-rows per block.
// 256 thr: tx=tid&7 owns j/d {tx*4, 32+tx*4}; ty=tid>>3 owns rows ty*4..+3.
// smem floats: smQ@0 [64d][128i]; smK@8192 [64d][64j]; smV@12288 [64j][64d];
//              smP@16384 [128i][68] (xs+Ws staging in Q-proj; P; ao).
// 98 KB dynamic smem, 128 regs -> 2 CTAs/SM. cp.async single-buffer staggered.
// ---------------------------------------------------------------------------
#define SMK_  8192
#define SMV_  12288
#define SMP_  16384
#define PP_   68
#define ATTN_SMEM ((SMP_ + 128 * PP_) * 4)   // 100352 B

__global__ void __launch_bounds__(256, 2)
attn_kernel(const float* __restrict__ x, const float* __restrict__ gamma,
            const float* __restrict__ beta, const float* __restrict__ w_qkv,
            const float* __restrict__ w_out, float* __restrict__ out,
            int half) {
    extern __shared__ float sm[];
    float* smQ = sm;
    float* smK = sm + SMK_;
    float* smV = sm + SMV_;
    float* smP = sm + SMP_;
    uint32_t smb = (uint32_t)__cvta_generic_to_shared(sm);

    int tid = threadIdx.x;
    int tx = tid & 7, ty = tid >> 3;          // ty in [0,32)
    int bb = blockIdx.y >> 3, h = blockIdx.y & 7;
    int b  = half * 2 + bb;
    int i0 = blockIdx.x * 128;

    const float* gK = g_kv + ((size_t)(bb * H_ + h) * DH_) * N_;
    const float* gV = g_kv + VOFF_ + ((size_t)(bb * H_ + h) * N_) * DH_;

    int ldj4 = (tid & 15) * 4;
    int ldk  = tid >> 4;

    // prefetch tile 0 (overlaps entire Q-projection)
    #pragma unroll
    for (int p = 0; p < 4; p++) {
        int d = ldk + p * 16;
        cp16(smb + (uint32_t)(SMK_ + d * 64 + ldj4) * 4, &gK[(size_t)d * N_ + ldj4]);
    }
    cp_commit();
    #pragma unroll
    for (int p = 0; p < 4; p++) {
        int j = ldk + p * 16;
        cp16(smb + (uint32_t)(SMV_ + j * 64 + ldj4) * 4, &gV[(size_t)j * DH_ + ldj4]);
    }
    cp_commit();

    // ---- Q-proj: Q[128,64] = LN(x) @ Wq[:,h*64..]; staging inside smP ----
    float* xs = smP;            // [32k][132] = 4224
    float* Ws = smP + 4224;     // [32k][64]  = 2048
    unsigned long long qa2[4][4];
    #pragma unroll
    for (int i = 0; i < 4; i++)
        #pragma unroll
        for (int q = 0; q < 4; q++) qa2[i][q] = 0ull;

    for (int kt = 0; kt < D_; kt += 32) {
        #pragma unroll
        for (int it = 0; it < 16; it++) {
            int e = tid + it * 256;
            int i = e >> 5, k = e & 31;
            int row = b * N_ + i0 + i;
            float xv = x[(size_t)row * D_ + kt + k];
            xs[k * 132 + i] = (xv - g_mu[row]) * g_rstd[row] * gamma[kt + k]
                              + beta[kt + k];
        }
        #pragma unroll
        for (int it = 0; it < 8; it++) {
            int e = tid + it * 256;
            int d = e & 63, k = e >> 6;
            Ws[k * 64 + d] = w_qkv[(size_t)(kt + k) * W3_ + h * DH_ + d];
        }
        __syncthreads();
        #pragma unroll
        for (int k = 0; k < 32; k++) {
            float4 aq = *(const float4*)&xs[k * 132 + ty * 4];
            ulonglong2 bL = *(const ulonglong2*)&Ws[k * 64 + tx * 4];
            ulonglong2 bH = *(const ulonglong2*)&Ws[k * 64 + 32 + tx * 4];
            unsigned long long a0 = bcast2(aq.x), a1 = bcast2(aq.y);
            unsigned long long a2 = bcast2(aq.z), a3 = bcast2(aq.w);
            ffma2(qa2[0][0], a0, bL.x); ffma2(qa2[0][1], a0, bL.y);
            ffma2(qa2[0][2], a0, bH.x); ffma2(qa2[0][3], a0, bH.y);
            ffma2(qa2[1][0], a1, bL.x); ffma2(qa2[1][1], a1, bL.y);
            ffma2(qa2[1][2], a1, bH.x); ffma2(qa2[1][3], a1, bH.y);
            ffma2(qa2[2][0], a2, bL.x); ffma2(qa2[2][1], a2, bL.y);
            ffma2(qa2[2][2], a2, bH.x); ffma2(qa2[2][3], a2, bH.y);
            ffma2(qa2[3][0], a3, bL.x); ffma2(qa2[3][1], a3, bL.y);
            ffma2(qa2[3][2], a3, bH.x); ffma2(qa2[3][3], a3, bH.y);
        }
        __syncthreads();
    }
    // smQ[d][i], pitch 128
    #pragma unroll
    for (int i = 0; i < 4; i++)
        #pragma unroll
        for (int q = 0; q < 4; q++) {
            F2U u; u.u = qa2[i][q];
            int d = ((q >> 1) ? 32 : 0) + tx * 4 + (q & 1) * 2;
            smQ[d * 128 + ty * 4 + i]       = u.f.x;
            smQ[(d + 1) * 128 + ty * 4 + i] = u.f.y;
        }

    // ---- attention over 32 j-tiles ----
    float lp[4] = {0.f, 0.f, 0.f, 0.f};
    unsigned long long o2[4][4];
    #pragma unroll
    for (int i = 0; i < 4; i++)
        #pragma unroll
        for (int q = 0; q < 4; q++) o2[i][q] = 0ull;

    for (int t = 0; t < NT_; t++) {
        cp_wait<1>();          // K(t) resident (V(t) may be in flight)
        __syncthreads();

        // S = Q K^T : 4i x 8j
        unsigned long long s2[4][4];
        #pragma unroll
        for (int i = 0; i < 4; i++)
            #pragma unroll
            for (int q = 0; q < 4; q++) s2[i][q] = 0ull;
        #pragma unroll 8
        for (int d = 0; d < 64; d++) {
            float4 aq = *(const float4*)&smQ[d * 128 + ty * 4];
            ulonglong2 kL = *(const ulonglong2*)&smK[d * 64 + tx * 4];
            ulonglong2 kH = *(const ulonglong2*)&smK[d * 64 + 32 + tx * 4];
            unsigned long long a0 = bcast2(aq.x), a1 = bcast2(aq.y);
            unsigned long long a2 = bcast2(aq.z), a3 = bcast2(aq.w);
            ffma2(s2[0][0], a0, kL.x); ffma2(s2[0][1], a0, kL.y);
            ffma2(s2[0][2], a0, kH.x); ffma2(s2[0][3], a0, kH.y);
            ffma2(s2[1][0], a1, kL.x); ffma2(s2[1][1], a1, kL.y);
            ffma2(s2[1][2], a1, kH.x); ffma2(s2[1][3], a1, kH.y);
            ffma2(s2[2][0], a2, kL.x); ffma2(s2[2][1], a2, kL.y);
            ffma2(s2[2][2], a2, kH.x); ffma2(s2[2][3], a2, kH.y);
            ffma2(s2[3][0], a3, kL.x); ffma2(s2[3][1], a3, kL.y);
            ffma2(s2[3][2], a3, kH.x); ffma2(s2[3][3], a3, kH.y);
        }
        __syncthreads();       // K reads done -> safe to refill smK

        if (t + 1 < NT_) {
            int j0n = (t + 1) * 64;
            #pragma unroll
            for (int p = 0; p < 4; p++) {
                int d = ldk + p * 16;
                cp16(smb + (uint32_t)(SMK_ + d * 64 + ldj4) * 4,
                     &gK[(size_t)d * N_ + j0n + ldj4]);
            }
            cp_commit();
        }

        // exp + partial l + stage P (rows ty*4+i, cols {tx*4, 32+tx*4})
        #pragma unroll
        for (int i = 0; i < 4; i++) {
            F2U u0, u1, u2, u3;
            u0.u = s2[i][0]; u1.u = s2[i][1]; u2.u = s2[i][2]; u3.u = s2[i][3];
            float p0 = exp2f(u0.f.x * KEXP_), p1 = exp2f(u0.f.y * KEXP_);
            float p2 = exp2f(u1.f.x * KEXP_), p3 = exp2f(u1.f.y * KEXP_);
            float p4 = exp2f(u2.f.x * KEXP_), p5 = exp2f(u2.f.y * KEXP_);
            float p6 = exp2f(u3.f.x * KEXP_), p7 = exp2f(u3.f.y * KEXP_);
            lp[i] += ((p0 + p1) + (p2 + p3)) + ((p4 + p5) + (p6 + p7));
            float* pr = &smP[(ty * 4 + i) * PP_];
            *(float4*)&pr[tx * 4]      = make_float4(p0, p1, p2, p3);
            *(float4*)&pr[32 + tx * 4] = make_float4(p4, p5, p6, p7);
        }
        cp_wait<1>();          // V(t) resident (K(t+1) may be in flight)
        __syncthreads();       // P visible + V visible to all

        // O += P V : 4i x 8d
        #pragma unroll 4
        for (int j4 = 0; j4 < 64; j4 += 4) {
            float4 pr0 = *(const float4*)&smP[(ty * 4 + 0) * PP_ + j4];
            float4 pr1 = *(const float4*)&smP[(ty * 4 + 1) * PP_ + j4];
            float4 pr2 = *(const float4*)&smP[(ty * 4 + 2) * PP_ + j4];
            float4 pr3 = *(const float4*)&smP[(ty * 4 + 3) * PP_ + j4];
            #pragma unroll
            for (int jj = 0; jj < 4; jj++) {
                ulonglong2 vL = *(const ulonglong2*)&smV[(j4 + jj) * 64 + tx * 4];
                ulonglong2 vH = *(const ulonglong2*)&smV[(j4 + jj) * 64 + 32 + tx * 4];
                float f0 = (jj == 0) ? pr0.x : (jj == 1) ? pr0.y : (jj == 2) ? pr0.z : pr0.w;
                float f1 = (jj == 0) ? pr1.x : (jj == 1) ? pr1.y : (jj == 2) ? pr1.z : pr1.w;
                float f2 = (jj == 0) ? pr2.x : (jj == 1) ? pr2.y : (jj == 2) ? pr2.z : pr2.w;
                float f3 = (jj == 0) ? pr3.x : (jj == 1) ? pr3.y : (jj == 2) ? pr3.z : pr3.w;
                unsigned long long b0 = bcast2(f0), b1 = bcast2(f1);
                unsigned long long b2 = bcast2(f2), b3 = bcast2(f3);
                ffma2(o2[0][0], b0, vL.x); ffma2(o2[0][1], b0, vL.y);
                ffma2(o2[0][2], b0, vH.x); ffma2(o2[0][3], b0, vH.y);
                ffma2(o2[1][0], b1, vL.x); ffma2(o2[1][1], b1, vL.y);
                ffma2(o2[1][2], b1, vH.x); ffma2(o2[1][3], b1, vH.y);
                ffma2(o2[2][0], b2, vL.x); ffma2(o2[2][1], b2, vL.y);
                ffma2(o2[2][2], b2, vH.x); ffma2(o2[2][3], b2, vH.y);
                ffma2(o2[3][0], b3, vL.x); ffma2(o2[3][1], b3, vL.y);
                ffma2(o2[3][2], b3, vH.x); ffma2(o2[3][3], b3, vH.y);
            }
        }
        __syncthreads();       // V & P reads done -> safe to refill smV / P

        if (t + 1 < NT_) {
            int j0n = (t + 1) * 64;
            #pragma unroll
            for (int p = 0; p < 4; p++) {
                int j = ldk + p * 16;
                cp16(smb + (uint32_t)(SMV_ + j * 64 + ldj4) * 4,
                     &gV[(size_t)(j0n + j) * DH_ + ldj4]);
            }
            cp_commit();
        }
    }

    // ---- finalize l: reduce over the 8 tx lanes sharing a row group ----
    #pragma unroll
    for (int i = 0; i < 4; i++) {
        #pragma unroll
        for (int off = 4; off > 0; off >>= 1)
            lp[i] += __shfl_xor_sync(0xffffffffu, lp[i], off);
    }

    // ao[i][d] into smP (pitch PP_)
    #pragma unroll
    for (int i = 0; i < 4; i++) {
        float inv = 1.0f / lp[i];
        F2U u0, u1, u2, u3;
        u0.u = o2[i][0]; u1.u = o2[i][1]; u2.u = o2[i][2]; u3.u = o2[i][3];
        float* pr = &smP[(ty * 4 + i) * PP_];
        *(float4*)&pr[tx * 4] =
            make_float4(u0.f.x * inv, u0.f.y * inv, u1.f.x * inv, u1.f.y * inv);
        *(float4*)&pr[32 + tx * 4] =
            make_float4(u2.f.x * inv, u2.f.y * inv, u3.f.x * inv, u3.f.y * inv);
    }

    // ---- out-proj: out += ao @ Wout[h*64..+63, :] ----
    float* Wo = smK;   // 64x64
    for (int nt = 0; nt < D_; nt += 64) {
        __syncthreads();
        #pragma unroll
        for (int it = 0; it < 4; it++) {
            int e = tid + it * 256;
            int n4 = (e & 15) * 4, d = e >> 4;
            *(float4*)&Wo[d * 64 + n4] =
                *(const float4*)&w_out[(size_t)(h * DH_ + d) * D_ + nt + n4];
        }
        __syncthreads();
        unsigned long long c2[4][4];
        #pragma unroll
        for (int i = 0; i < 4; i++)
            #pragma unroll
            for (int q = 0; q < 4; q++) c2[i][q] = 0ull;
        #pragma unroll 8
        for (int d = 0; d < 64; d++) {
            ulonglong2 wL = *(const ulonglong2*)&Wo[d * 64 + tx * 4];
            ulonglong2 wH = *(const ulonglong2*)&Wo[d * 64 + 32 + tx * 4];
            unsigned long long a0 = bcast2(smP[(ty * 4 + 0) * PP_ + d]);
            unsigned long long a1 = bcast2(smP[(ty * 4 + 1) * PP_ + d]);
            unsigned long long a2 = bcast2(smP[(ty * 4 + 2) * PP_ + d]);
            unsigned long long a3 = bcast2(smP[(ty * 4 + 3) * PP_ + d]);
            ffma2(c2[0][0], a0, wL.x); ffma2(c2[0][1], a0, wL.y);
            ffma2(c2[0][2], a0, wH.x); ffma2(c2[0][3], a0, wH.y);
            ffma2(c2[1][0], a1, wL.x); ffma2(c2[1][1], a1, wL.y);
            ffma2(c2[1][2], a1, wH.x); ffma2(c2[1][3], a1, wH.y);
            ffma2(c2[2][0], a2, wL.x); ffma2(c2[2][1], a2, wL.y);
            ffma2(c2[2][2], a2, wH.x); ffma2(c2[2][3], a2, wH.y);
            ffma2(c2[3][0], a3, wL.x); ffma2(c2[3][1], a3, wL.y);
            ffma2(c2[3][2], a3, wH.x); ffma2(c2[3][3], a3, wH.y);
        }
        #pragma unroll
        for (int i = 0; i < 4; i++) {
            size_t rbase = (size_t)(b * N_ + i0 + ty * 4 + i) * D_ + nt;
            #pragma unroll
            for (int q = 0; q < 4; q++) {
                F2U u; u.u = c2[i][q];
                int n = ((q >> 1) ? 32 : 0) + tx * 4 + (q & 1) * 2;
                atomicAdd(&out[rbase + n],     u.f.x);
                atomicAdd(&out[rbase + n + 1], u.f.y);
            }
        }
    }
}

// ---------------------------------------------------------------------------
extern "C" void kernel_launch(void* const* d_in, const int* in_sizes, int n_in,
                              void* d_out, int out_size) {
    const float* x     = (const float*)d_in[0];
    const float* gamma = (const float*)d_in[1];
    const float* beta  = (const float*)d_in[2];
    const float* w_qkv = (const float*)d_in[3];
    const float* w_out = (const float*)d_in[4];
    float* out = (float*)d_out;
    (void)in_sizes; (void)n_in; (void)out_size;

    cudaFuncSetAttribute(attn_kernel,
                         cudaFuncAttributeMaxDynamicSharedMemorySize,
                         ATTN_SMEM);

    zero_out_kernel<<<ROWS_ * D_ / 1024, 256>>>((float4*)out);
    ln_stats_kernel<<<ROWS_, 128>>>(x);

    for (int half = 0; half < 2; half++) {
        kvproj_kernel<<<dim3(2 * D_ / BN, 2 * N_ / BM), 256>>>(
            x, gamma, beta, w_qkv, half);
        attn_kernel<<<dim3(N_ / 128, 2 * H_), 256, ATTN_SMEM>>>(
            x, gamma, beta, w_qkv, w_out, out, half);
    }
}

// round 13
// speedup vs baseline: 1.7336x; 1.5951x over previous
#include <cuda_runtime.h>
#include <cstdint>

#define B_      4
#define N_      2048
#define D_      512
#define H_      8
#define DH_     64
#define ROWS_   (B_ * N_)
#define W3_     1536
#define KEXP_   0.18033688011112042f   // 64^-0.5 * log2(e)
#define NT_     (N_ / 64)

// ---------------------------------------------------------------------------
// Scratch: K natural [bbh][n][d], V transposed [bbh][d][n], bf16 hi/lo planes.
// 4 planes x 4MB = 16MB (reused across two half-batch rounds).
// ---------------------------------------------------------------------------
#define PLANE_  (16 * 2048 * 64)
__device__ unsigned short g_kh[PLANE_];
__device__ unsigned short g_kl[PLANE_];
__device__ unsigned short g_vh[PLANE_];
__device__ unsigned short g_vl[PLANE_];
__device__ float g_mu[ROWS_];
__device__ float g_rstd[ROWS_];

// ---------------------------------------------------------------------------
// helpers
// ---------------------------------------------------------------------------
__device__ __forceinline__ unsigned long long bcast2(float v) {
    unsigned long long r; unsigned int x = __float_as_uint(v);
    asm("mov.b64 %0, {%1, %2};" : "=l"(r) : "r"(x), "r"(x));
    return r;
}
__device__ __forceinline__ void ffma2(unsigned long long& d,
                                      unsigned long long a,
                                      unsigned long long b) {
    asm("fma.rn.f32x2 %0, %1, %2, %0;" : "+l"(d) : "l"(a), "l"(b));
}
union F2U { unsigned long long u; float2 f; };

__device__ __forceinline__ uint32_t pack_bf2(float lo_elem, float hi_elem) {
    uint32_t r;
    asm("cvt.rn.bf16x2.f32 %0, %1, %2;" : "=r"(r) : "f"(hi_elem), "f"(lo_elem));
    return r;   // low 16 bits = lo_elem
}
__device__ __forceinline__ float bf2lo(uint32_t p) { return __uint_as_float(p << 16); }
__device__ __forceinline__ float bf2hi(uint32_t p) { return __uint_as_float(p & 0xffff0000u); }
__device__ __forceinline__ void split2(float x0, float x1, uint32_t& hi, uint32_t& lo) {
    hi = pack_bf2(x0, x1);
    lo = pack_bf2(x0 - bf2lo(hi), x1 - bf2hi(hi));
}
__device__ __forceinline__ float ex2(float x) {
    float r; asm("ex2.approx.f32 %0, %1;" : "=f"(r) : "f"(x)); return r;
}

__device__ __forceinline__ void ldsm4(uint32_t addr, uint32_t& r0, uint32_t& r1,
                                      uint32_t& r2, uint32_t& r3) {
    asm volatile("ldmatrix.sync.aligned.m8n8.x4.shared.b16 {%0,%1,%2,%3}, [%4];"
                 : "=r"(r0), "=r"(r1), "=r"(r2), "=r"(r3) : "r"(addr));
}
__device__ __forceinline__ void mma_bf16(float& c0, float& c1, float& c2, float& c3,
                                         uint32_t a0, uint32_t a1, uint32_t a2, uint32_t a3,
                                         uint32_t b0, uint32_t b1) {
    asm volatile("mma.sync.aligned.m16n8k16.row.col.f32.bf16.bf16.f32 "
                 "{%0,%1,%2,%3}, {%4,%5,%6,%7}, {%8,%9}, {%0,%1,%2,%3};"
                 : "+f"(c0), "+f"(c1), "+f"(c2), "+f"(c3)
                 : "r"(a0), "r"(a1), "r"(a2), "r"(a3), "r"(b0), "r"(b1));
}

__device__ __forceinline__ void cp16(uint32_t dst, const void* src) {
    asm volatile("cp.async.cg.shared.global [%0], [%1], 16;" :: "r"(dst), "l"(src));
}
__device__ __forceinline__ void cp_commit() {
    asm volatile("cp.async.commit_group;");
}
template <int NN>
__device__ __forceinline__ void cp_wait() {
    asm volatile("cp.async.wait_group %0;" :: "n"(NN) : "memory");
}

__global__ void __launch_bounds__(256, 1) zero_out_kernel(float4* o) {
    o[blockIdx.x * 256 + threadIdx.x] = make_float4(0.f, 0.f, 0.f, 0.f);
}

__global__ void __launch_bounds__(128, 1)
ln_stats_kernel(const float* __restrict__ x) {
    int row = blockIdx.x;
    float4 v = reinterpret_cast<const float4*>(x + (size_t)row * D_)[threadIdx.x];
    float s  = v.x + v.y + v.z + v.w;
    float s2 = v.x * v.x + v.y * v.y + v.z * v.z + v.w * v.w;
    #pragma unroll
    for (int off = 16; off > 0; off >>= 1) {
        s  += __shfl_xor_sync(0xffffffffu, s,  off);
        s2 += __shfl_xor_sync(0xffffffffu, s2, off);
    }
    __shared__ float sh[8];
    int w = threadIdx.x >> 5;
    if ((threadIdx.x & 31) == 0) { sh[w] = s; sh[w + 4] = s2; }
    __syncthreads();
    if (threadIdx.x == 0) {
        s  = sh[0] + sh[1] + sh[2] + sh[3];
        s2 = sh[4] + sh[5] + sh[6] + sh[7];
        float mu  = s * (1.0f / D_);
        float var = s2 * (1.0f / D_) - mu * mu;
        g_mu[row] = mu; g_rstd[row] = rsqrtf(var + 1e-5f);
    }
}

// --------------------------- KV projection ---------------------------------
// Same GEMM as before; epilogue now writes bf16 hi/lo planes:
//   K natural [bbh][n][d], V transposed [bbh][d][n].
#define BM 128
#define BN 128
#define BK 16

__global__ void __launch_bounds__(256, 1)
kvproj_kernel(const float* __restrict__ x, const float* __restrict__ gamma,
              const float* __restrict__ beta, const float* __restrict__ W,
              int half) {
    __shared__ float As[BK][BM];
    __shared__ float Bs[BK][BN];
    int tid = threadIdx.x;
    int tx = tid & 15, ty = tid >> 4;
    int m0 = half * (2 * N_) + blockIdx.y * BM;
    int n0 = D_ + blockIdx.x * BN;

    float acc[8][8];
    #pragma unroll
    for (int i = 0; i < 8; i++)
        #pragma unroll
        for (int j = 0; j < 8; j++) acc[i][j] = 0.f;

    for (int kt = 0; kt < D_; kt += BK) {
        #pragma unroll
        for (int i = 0; i < 8; i++) {
            int e = tid + i * 256;
            int m = e >> 4, kk = e & 15;
            int row = m0 + m;
            float xv = x[(size_t)row * D_ + kt + kk];
            xv = (xv - g_mu[row]) * g_rstd[row] * gamma[kt + kk] + beta[kt + kk];
            As[kk][m] = xv;
        }
        #pragma unroll
        for (int i = 0; i < 8; i++) {
            int e = tid + i * 256;
            int kk = e >> 7, n = e & 127;
            Bs[kk][n] = W[(size_t)(kt + kk) * W3_ + n0 + n];
        }
        __syncthreads();
        #pragma unroll
        for (int k = 0; k < BK; k++) {
            float4 a0 = *(const float4*)&As[k][ty * 8];
            float4 a1 = *(const float4*)&As[k][ty * 8 + 4];
            float4 b0 = *(const float4*)&Bs[k][tx * 8];
            float4 b1 = *(const float4*)&Bs[k][tx * 8 + 4];
            float av[8] = {a0.x, a0.y, a0.z, a0.w, a1.x, a1.y, a1.z, a1.w};
            float bv[8] = {b0.x, b0.y, b0.z, b0.w, b1.x, b1.y, b1.z, b1.w};
            #pragma unroll
            for (int i = 0; i < 8; i++)
                #pragma unroll
                for (int j = 0; j < 8; j++)
                    acc[i][j] = fmaf(av[i], bv[j], acc[i][j]);
        }
        __syncthreads();
    }

    int col_rel = (n0 - D_) + tx * 8;
    int kvsel = col_rel >> 9, within = col_rel & 511;
    int h = within >> 6, d0 = within & 63;
    int r0 = m0 + ty * 8;
    int bb = (r0 >> 11) & 1;            // 8 consecutive rows share bb
    int nb = r0 & (N_ - 1);
    int bbh = bb * H_ + h;
    if (kvsel == 0) {
        // K natural [n][d]: per row i, 8 contiguous d -> 16B hi + 16B lo
        #pragma unroll
        for (int i = 0; i < 8; i++) {
            uint32_t hp[4], lp[4];
            #pragma unroll
            for (int jp = 0; jp < 4; jp++)
                split2(acc[i][2 * jp], acc[i][2 * jp + 1], hp[jp], lp[jp]);
            size_t kb = ((size_t)bbh * N_ + nb + i) * DH_ + d0;
            *(uint4*)&g_kh[kb] = make_uint4(hp[0], hp[1], hp[2], hp[3]);
            *(uint4*)&g_kl[kb] = make_uint4(lp[0], lp[1], lp[2], lp[3]);
        }
    } else {
        // V transposed [d][n]: per col j (=d), 8 contiguous n -> 16B
        #pragma unroll
        for (int j = 0; j < 8; j++) {
            uint32_t hp[4], lp[4];
            #pragma unroll
            for (int ip = 0; ip < 4; ip++)
                split2(acc[2 * ip][j], acc[2 * ip + 1][j], hp[ip], lp[ip]);
            size_t vb = ((size_t)bbh * DH_ + d0 + j) * N_ + nb;
            *(uint4*)&g_vh[vb] = make_uint4(hp[0], hp[1], hp[2], hp[3]);
            *(uint4*)&g_vl[vb] = make_uint4(lp[0], lp[1], lp[2], lp[3]);
        }
    }
}

// ---------------------------------------------------------------------------
// Kernel D: fused Q-proj (FFMA2) + tensor-core attention (bf16x3 mma) +
//           out-proj (FFMA2). 128 q-rows per block, 8 warps (16 rows each).
//
// smem bytes:
//   [0,18432)      Qhi plane [128][72] bf16   (later: ao f32 [128][68])
//   [18432,36864)  Qlo plane
//   [36864,73728)  tile buffer 0: Khi|Klo|Vhi|Vlo, each [64][72] bf16 (9216B)
//   [73728,110592) tile buffer 1 (also xs/Ws staging during Q-proj)
// ---------------------------------------------------------------------------
#define QSTB_   36864
#define BUFB_   36864
#define ATTN_SMEM (QSTB_ + 2 * BUFB_)   // 110592

__global__ void __launch_bounds__(256, 2)
attn_kernel(const float* __restrict__ x, const float* __restrict__ gamma,
            const float* __restrict__ beta, const float* __restrict__ w_qkv,
            const float* __restrict__ w_out, float* __restrict__ out,
            int half) {
    extern __shared__ char smc[];
    float* smf = (float*)smc;
    uint32_t smb = (uint32_t)__cvta_generic_to_shared(smc);

    int tid = threadIdx.x;
    int tx = tid & 7, ty = tid >> 3;          // Q-proj / out-proj mapping
    int lane = tid & 31;
    int w = tid >> 5;
    int g = lane >> 2, tig = lane & 3;
    int bb = blockIdx.y >> 3, h = blockIdx.y & 7;
    int b  = half * 2 + bb;
    int i0 = blockIdx.x * 128;
    int bbh = bb * H_ + h;

    const unsigned short* kh = g_kh + (size_t)bbh * N_ * DH_;
    const unsigned short* kl = g_kl + (size_t)bbh * N_ * DH_;
    const unsigned short* vh = g_vh + (size_t)bbh * DH_ * N_;
    const unsigned short* vl = g_vl + (size_t)bbh * DH_ * N_;

    // ---- prefetch tile 0 into buffer 0 (group 0) ----
    {
        uint32_t bufb = smb + QSTB_;
        #pragma unroll
        for (int c = 0; c < 2; c++) {
            int cid = tid + c * 256;
            int n = cid >> 3, c8 = (cid & 7) * 8;
            uint32_t so = (uint32_t)(n * 72 + c8) * 2;
            cp16(bufb + so,         kh + (size_t)n * DH_ + c8);
            cp16(bufb + 9216 + so,  kl + (size_t)n * DH_ + c8);
            cp16(bufb + 18432 + so, vh + (size_t)n * N_ + c8);
            cp16(bufb + 27648 + so, vl + (size_t)n * N_ + c8);
        }
        cp_commit();
    }

    // ---- Q-proj: Q[128,64] = LN(x) @ Wq[:,h*64..], FFMA2; staging in buf1 ----
    {
        float* xs = smf + (QSTB_ + BUFB_) / 4;   // [32][132]
        float* Ws = xs + 4224;                   // [32][64]
        unsigned long long qa2[4][4];
        #pragma unroll
        for (int i = 0; i < 4; i++)
            #pragma unroll
            for (int q = 0; q < 4; q++) qa2[i][q] = 0ull;

        for (int kt = 0; kt < D_; kt += 32) {
            #pragma unroll
            for (int it = 0; it < 16; it++) {
                int e = tid + it * 256;
                int i = e >> 5, k = e & 31;
                int row = b * N_ + i0 + i;
                float xv = x[(size_t)row * D_ + kt + k];
                xs[k * 132 + i] = (xv - g_mu[row]) * g_rstd[row] * gamma[kt + k]
                                  + beta[kt + k];
            }
            #pragma unroll
            for (int it = 0; it < 8; it++) {
                int e = tid + it * 256;
                int d = e & 63, k = e >> 6;
                Ws[k * 64 + d] = w_qkv[(size_t)(kt + k) * W3_ + h * DH_ + d];
            }
            __syncthreads();
            #pragma unroll
            for (int k = 0; k < 32; k++) {
                float4 aq = *(const float4*)&xs[k * 132 + ty * 4];
                ulonglong2 bL = *(const ulonglong2*)&Ws[k * 64 + tx * 4];
                ulonglong2 bH = *(const ulonglong2*)&Ws[k * 64 + 32 + tx * 4];
                unsigned long long a0 = bcast2(aq.x), a1 = bcast2(aq.y);
                unsigned long long a2 = bcast2(aq.z), a3 = bcast2(aq.w);
                ffma2(qa2[0][0], a0, bL.x); ffma2(qa2[0][1], a0, bL.y);
                ffma2(qa2[0][2], a0, bH.x); ffma2(qa2[0][3], a0, bH.y);
                ffma2(qa2[1][0], a1, bL.x); ffma2(qa2[1][1], a1, bL.y);
                ffma2(qa2[1][2], a1, bH.x); ffma2(qa2[1][3], a1, bH.y);
                ffma2(qa2[2][0], a2, bL.x); ffma2(qa2[2][1], a2, bL.y);
                ffma2(qa2[2][2], a2, bH.x); ffma2(qa2[2][3], a2, bH.y);
                ffma2(qa2[3][0], a3, bL.x); ffma2(qa2[3][1], a3, bL.y);
                ffma2(qa2[3][2], a3, bH.x); ffma2(qa2[3][3], a3, bH.y);
            }
            __syncthreads();
        }
        // store Q hi/lo bf16 planes [128][72]
        #pragma unroll
        for (int i = 0; i < 4; i++)
            #pragma unroll
            for (int q = 0; q < 4; q++) {
                F2U u; u.u = qa2[i][q];
                int d = ((q >> 1) ? 32 : 0) + tx * 4 + (q & 1) * 2;
                int row = ty * 4 + i;
                uint32_t hp, lp;
                split2(u.f.x, u.f.y, hp, lp);
                *(uint32_t*)(smc + (row * 72 + d) * 2)         = hp;
                *(uint32_t*)(smc + 18432 + (row * 72 + d) * 2) = lp;
            }
    }
    __syncthreads();

    // ---- prefetch tile 1 into buffer 1 (group 1) ----
    {
        uint32_t bufb = smb + QSTB_ + BUFB_;
        #pragma unroll
        for (int c = 0; c < 2; c++) {
            int cid = tid + c * 256;
            int n = cid >> 3, c8 = (cid & 7) * 8;
            uint32_t so = (uint32_t)(n * 72 + c8) * 2;
            cp16(bufb + so,         kh + (size_t)(64 + n) * DH_ + c8);
            cp16(bufb + 9216 + so,  kl + (size_t)(64 + n) * DH_ + c8);
            cp16(bufb + 18432 + so, vh + (size_t)n * N_ + 64 + c8);
            cp16(bufb + 27648 + so, vl + (size_t)n * N_ + 64 + c8);
        }
        cp_commit();
    }

    // ---- load Q fragments (A-frags, m16n8k16) ----
    uint32_t qh[4][4], ql[4][4];
    {
        uint32_t qrow = 16 * w + (lane & 15);
        uint32_t qcol = (lane >> 4) * 8;
        #pragma unroll
        for (int kk = 0; kk < 4; kk++) {
            uint32_t off = (qrow * 72 + 16 * kk + qcol) * 2;
            ldsm4(smb + off,          qh[kk][0], qh[kk][1], qh[kk][2], qh[kk][3]);
            ldsm4(smb + 18432 + off,  ql[kk][0], ql[kk][1], ql[kk][2], ql[kk][3]);
        }
    }

    // B-frag lane offsets (shared by K and V ldmatrix)
    uint32_t bn = (lane & 7) + ((lane & 16) ? 8 : 0);
    uint32_t bkof = (lane & 8) ? 8 : 0;

    float oc[8][4];
    #pragma unroll
    for (int dt = 0; dt < 8; dt++)
        #pragma unroll
        for (int q = 0; q < 4; q++) oc[dt][q] = 0.f;
    float lpg = 0.f, lpg8 = 0.f;

    for (int t = 0; t < NT_; t++) {
        if (t == NT_ - 1) cp_wait<0>(); else cp_wait<1>();
        __syncthreads();
        uint32_t bufb = smb + QSTB_ + (uint32_t)(t & 1) * BUFB_;
        uint32_t kbh = bufb, kbl = bufb + 9216;
        uint32_t vbh = bufb + 18432, vbl = bufb + 27648;

        #pragma unroll
        for (int hf = 0; hf < 2; hf++) {
            // S = Q K^T over 4 n-tiles (j = 32*hf .. +32)
            float sc[4][4];
            #pragma unroll
            for (int nt = 0; nt < 4; nt++)
                #pragma unroll
                for (int q = 0; q < 4; q++) sc[nt][q] = 0.f;

            #pragma unroll
            for (int kk = 0; kk < 4; kk++) {
                #pragma unroll
                for (int ap = 0; ap < 2; ap++) {
                    uint32_t koff = ((32 * hf + 16 * ap + bn) * 72 + 16 * kk + bkof) * 2;
                    uint32_t h0, h1, h2, h3, l0, l1, l2, l3;
                    ldsm4(kbh + koff, h0, h1, h2, h3);
                    ldsm4(kbl + koff, l0, l1, l2, l3);
                    int n0t = 2 * ap, n1t = 2 * ap + 1;
                    mma_bf16(sc[n0t][0], sc[n0t][1], sc[n0t][2], sc[n0t][3],
                             qh[kk][0], qh[kk][1], qh[kk][2], qh[kk][3], h0, h1);
                    mma_bf16(sc[n0t][0], sc[n0t][1], sc[n0t][2], sc[n0t][3],
                             qh[kk][0], qh[kk][1], qh[kk][2], qh[kk][3], l0, l1);
                    mma_bf16(sc[n0t][0], sc[n0t][1], sc[n0t][2], sc[n0t][3],
                             ql[kk][0], ql[kk][1], ql[kk][2], ql[kk][3], h0, h1);
                    mma_bf16(sc[n1t][0], sc[n1t][1], sc[n1t][2], sc[n1t][3],
                             qh[kk][0], qh[kk][1], qh[kk][2], qh[kk][3], h2, h3);
                    mma_bf16(sc[n1t][0], sc[n1t][1], sc[n1t][2], sc[n1t][3],
                             qh[kk][0], qh[kk][1], qh[kk][2], qh[kk][3], l2, l3);
                    mma_bf16(sc[n1t][0], sc[n1t][1], sc[n1t][2], sc[n1t][3],
                             ql[kk][0], ql[kk][1], ql[kk][2], ql[kk][3], h2, h3);
                }
            }

            // softmax piece + PV, one 16-j k-step at a time
            #pragma unroll
            for (int k2 = 0; k2 < 2; k2++) {
                uint32_t pa_h[4], pa_l[4];
                #pragma unroll
                for (int e = 0; e < 2; e++) {       // ntl = 2*k2 + e
                    int nt = 2 * k2 + e;
                    float p0 = ex2(sc[nt][0] * KEXP_);
                    float p1 = ex2(sc[nt][1] * KEXP_);
                    float p2 = ex2(sc[nt][2] * KEXP_);
                    float p3 = ex2(sc[nt][3] * KEXP_);
                    lpg  += p0 + p1;
                    lpg8 += p2 + p3;
                    uint32_t h01, l01, h23, l23;
                    split2(p0, p1, h01, l01);
                    split2(p2, p3, h23, l23);
                    pa_h[2 * e] = h01; pa_h[2 * e + 1] = h23;
                    pa_l[2 * e] = l01; pa_l[2 * e + 1] = l23;
                }
                #pragma unroll
                for (int a = 0; a < 4; a++) {
                    uint32_t voff = ((16 * a + bn) * 72 + 32 * hf + 16 * k2 + bkof) * 2;
                    uint32_t h0, h1, h2, h3, l0, l1, l2, l3;
                    ldsm4(vbh + voff, h0, h1, h2, h3);
                    ldsm4(vbl + voff, l0, l1, l2, l3);
                    int d0t = 2 * a, d1t = 2 * a + 1;
                    mma_bf16(oc[d0t][0], oc[d0t][1], oc[d0t][2], oc[d0t][3],
                             pa_h[0], pa_h[1], pa_h[2], pa_h[3], h0, h1);
                    mma_bf16(oc[d0t][0], oc[d0t][1], oc[d0t][2], oc[d0t][3],
                             pa_h[0], pa_h[1], pa_h[2], pa_h[3], l0, l1);
                    mma_bf16(oc[d0t][0], oc[d0t][1], oc[d0t][2], oc[d0t][3],
                             pa_l[0], pa_l[1], pa_l[2], pa_l[3], h0, h1);
                    mma_bf16(oc[d1t][0], oc[d1t][1], oc[d1t][2], oc[d1t][3],
                             pa_h[0], pa_h[1], pa_h[2], pa_h[3], h2, h3);
                    mma_bf16(oc[d1t][0], oc[d1t][1], oc[d1t][2], oc[d1t][3],
                             pa_h[0], pa_h[1], pa_h[2], pa_h[3], l2, l3);
                    mma_bf16(oc[d1t][0], oc[d1t][1], oc[d1t][2], oc[d1t][3],
                             pa_l[0], pa_l[1], pa_l[2], pa_l[3], h2, h3);
                }
            }
        }
        __syncthreads();   // all warps done reading buf(t&1)

        if (t + 2 < NT_) {
            int j0n = (t + 2) * 64;
            #pragma unroll
            for (int c = 0; c < 2; c++) {
                int cid = tid + c * 256;
                int n = cid >> 3, c8 = (cid & 7) * 8;
                uint32_t so = (uint32_t)(n * 72 + c8) * 2;
                cp16(bufb + so,         kh + (size_t)(j0n + n) * DH_ + c8);
                cp16(bufb + 9216 + so,  kl + (size_t)(j0n + n) * DH_ + c8);
                cp16(bufb + 18432 + so, vh + (size_t)n * N_ + j0n + c8);
                cp16(bufb + 27648 + so, vl + (size_t)n * N_ + j0n + c8);
            }
            cp_commit();
        }
    }

    // ---- finalize l (reduce over the 4 lanes of each quad) ----
    lpg  += __shfl_xor_sync(0xffffffffu, lpg, 1);
    lpg  += __shfl_xor_sync(0xffffffffu, lpg, 2);
    lpg8 += __shfl_xor_sync(0xffffffffu, lpg8, 1);
    lpg8 += __shfl_xor_sync(0xffffffffu, lpg8, 2);
    float invg = 1.0f / lpg, invg8 = 1.0f / lpg8;

    // ---- write ao f32 [128][68] (aliases Q staging; Q frags already in regs)
    float* ao = smf;
    {
        int row = 16 * w + g;
        #pragma unroll
        for (int dt = 0; dt < 8; dt++) {
            int col = 8 * dt + 2 * tig;
            *(float2*)&ao[row * 68 + col] =
                make_float2(oc[dt][0] * invg, oc[dt][1] * invg);
            *(float2*)&ao[(row + 8) * 68 + col] =
                make_float2(oc[dt][2] * invg8, oc[dt][3] * invg8);
        }
    }

    // ---- out-proj: out += ao @ Wout[h*64..+63, :], FFMA2 + atomicAdd ----
    float* Wo = smf + QSTB_ / 4;   // buffer0 region (all cp.async complete)
    for (int nt = 0; nt < D_; nt += 64) {
        __syncthreads();
        #pragma unroll
        for (int it = 0; it < 4; it++) {
            int e = tid + it * 256;
            int n4 = (e & 15) * 4, d = e >> 4;
            *(float4*)&Wo[d * 64 + n4] =
                *(const float4*)&w_out[(size_t)(h * DH_ + d) * D_ + nt + n4];
        }
        __syncthreads();
        unsigned long long c2[4][4];
        #pragma unroll
        for (int i = 0; i < 4; i++)
            #pragma unroll
            for (int q = 0; q < 4; q++) c2[i][q] = 0ull;
        #pragma unroll 8
        for (int d = 0; d < 64; d++) {
            ulonglong2 wL = *(const ulonglong2*)&Wo[d * 64 + tx * 4];
            ulonglong2 wH = *(const ulonglong2*)&Wo[d * 64 + 32 + tx * 4];
            unsigned long long a0 = bcast2(ao[(ty * 4 + 0) * 68 + d]);
            unsigned long long a1 = bcast2(ao[(ty * 4 + 1) * 68 + d]);
            unsigned long long a2 = bcast2(ao[(ty * 4 + 2) * 68 + d]);
            unsigned long long a3 = bcast2(ao[(ty * 4 + 3) * 68 + d]);
            ffma2(c2[0][0], a0, wL.x); ffma2(c2[0][1], a0, wL.y);
            ffma2(c2[0][2], a0, wH.x); ffma2(c2[0][3], a0, wH.y);
            ffma2(c2[1][0], a1, wL.x); ffma2(c2[1][1], a1, wL.y);
            ffma2(c2[1][2], a1, wH.x); ffma2(c2[1][3], a1, wH.y);
            ffma2(c2[2][0], a2, wL.x); ffma2(c2[2][1], a2, wL.y);
            ffma2(c2[2][2], a2, wH.x); ffma2(c2[2][3], a2, wH.y);
            ffma2(c2[3][0], a3, wL.x); ffma2(c2[3][1], a3, wL.y);
            ffma2(c2[3][2], a3, wH.x); ffma2(c2[3][3], a3, wH.y);
        }
        #pragma unroll
        for (int i = 0; i < 4; i++) {
            size_t rbase = (size_t)(b * N_ + i0 + ty * 4 + i) * D_ + nt;
            #pragma unroll
            for (int q = 0; q < 4; q++) {
                F2U u; u.u = c2[i][q];
                int n = ((q >> 1) ? 32 : 0) + tx * 4 + (q & 1) * 2;
                atomicAdd(&out[rbase + n],     u.f.x);
                atomicAdd(&out[rbase + n + 1], u.f.y);
            }
        }
    }
}

// ---------------------------------------------------------------------------
extern "C" void kernel_launch(void* const* d_in, const int* in_sizes, int n_in,
                              void* d_out, int out_size) {
    const float* x     = (const float*)d_in[0];
    const float* gamma = (const float*)d_in[1];
    const float* beta  = (const float*)d_in[2];
    const float* w_qkv = (const float*)d_in[3];
    const float* w_out = (const float*)d_in[4];
    float* out = (float*)d_out;
    (void)in_sizes; (void)n_in; (void)out_size;

    cudaFuncSetAttribute(attn_kernel,
                         cudaFuncAttributeMaxDynamicSharedMemorySize,
                         ATTN_SMEM);

    zero_out_kernel<<<ROWS_ * D_ / 1024, 256>>>((float4*)out);
    ln_stats_kernel<<<ROWS_, 128>>>(x);

    for (int half = 0; half < 2; half++) {
        kvproj_kernel<<<dim3(2 * D_ / BN, 2 * N_ / BM), 256>>>(
            x, gamma, beta, w_qkv, half);
        attn_kernel<<<dim3(N_ / 128, 2 * H_), 256, ATTN_SMEM>>>(
            x, gamma, beta, w_qkv, w_out, out, half);
    }
}

// round 14
// speedup vs baseline: 1.7938x; 1.0347x over previous
#include <cuda_runtime.h>
#include <cstdint>

#define B_      4
#define N_      2048
#define D_      512
#define H_      8
#define DH_     64
#define ROWS_   (B_ * N_)
#define W3_     1536
#define KEXP_   0.18033688011112042f   // 64^-0.5 * log2(e)
#define NT_     (N_ / 64)

// ---------------------------------------------------------------------------
// Scratch: K natural [bbh][n][d], V transposed [bbh][d][n], bf16 hi/lo planes.
// 4 planes x 4MB = 16MB (reused across two half-batch rounds).
// ---------------------------------------------------------------------------
#define PLANE_  (16 * 2048 * 64)
__device__ unsigned short g_kh[PLANE_];
__device__ unsigned short g_kl[PLANE_];
__device__ unsigned short g_vh[PLANE_];
__device__ unsigned short g_vl[PLANE_];
__device__ float g_mu[ROWS_];
__device__ float g_rstd[ROWS_];

// ---------------------------------------------------------------------------
// helpers
// ---------------------------------------------------------------------------
__device__ __forceinline__ unsigned long long bcast2(float v) {
    unsigned long long r; unsigned int x = __float_as_uint(v);
    asm("mov.b64 %0, {%1, %2};" : "=l"(r) : "r"(x), "r"(x));
    return r;
}
__device__ __forceinline__ void ffma2(unsigned long long& d,
                                      unsigned long long a,
                                      unsigned long long b) {
    asm("fma.rn.f32x2 %0, %1, %2, %0;" : "+l"(d) : "l"(a), "l"(b));
}
union F2U { unsigned long long u; float2 f; };

__device__ __forceinline__ uint32_t pack_bf2(float lo_elem, float hi_elem) {
    uint32_t r;
    asm("cvt.rn.bf16x2.f32 %0, %1, %2;" : "=r"(r) : "f"(hi_elem), "f"(lo_elem));
    return r;   // low 16 bits = lo_elem
}
__device__ __forceinline__ float bf2lo(uint32_t p) { return __uint_as_float(p << 16); }
__device__ __forceinline__ float bf2hi(uint32_t p) { return __uint_as_float(p & 0xffff0000u); }
__device__ __forceinline__ void split2(float x0, float x1, uint32_t& hi, uint32_t& lo) {
    hi = pack_bf2(x0, x1);
    lo = pack_bf2(x0 - bf2lo(hi), x1 - bf2hi(hi));
}
__device__ __forceinline__ float ex2(float x) {
    float r; asm("ex2.approx.f32 %0, %1;" : "=f"(r) : "f"(x)); return r;
}

__device__ __forceinline__ void ldsm4(uint32_t addr, uint32_t& r0, uint32_t& r1,
                                      uint32_t& r2, uint32_t& r3) {
    asm volatile("ldmatrix.sync.aligned.m8n8.x4.shared.b16 {%0,%1,%2,%3}, [%4];"
                 : "=r"(r0), "=r"(r1), "=r"(r2), "=r"(r3) : "r"(addr));
}
__device__ __forceinline__ void mma_bf16(float& c0, float& c1, float& c2, float& c3,
                                         uint32_t a0, uint32_t a1, uint32_t a2, uint32_t a3,
                                         uint32_t b0, uint32_t b1) {
    asm volatile("mma.sync.aligned.m16n8k16.row.col.f32.bf16.bf16.f32 "
                 "{%0,%1,%2,%3}, {%4,%5,%6,%7}, {%8,%9}, {%0,%1,%2,%3};"
                 : "+f"(c0), "+f"(c1), "+f"(c2), "+f"(c3)
                 : "r"(a0), "r"(a1), "r"(a2), "r"(a3), "r"(b0), "r"(b1));
}

__device__ __forceinline__ void cp16(uint32_t dst, const void* src) {
    asm volatile("cp.async.cg.shared.global [%0], [%1], 16;" :: "r"(dst), "l"(src));
}
__device__ __forceinline__ void cp_commit() {
    asm volatile("cp.async.commit_group;");
}
template <int NN>
__device__ __forceinline__ void cp_wait() {
    asm volatile("cp.async.wait_group %0;" :: "n"(NN) : "memory");
}

__global__ void __launch_bounds__(256, 1) zero_out_kernel(float4* o) {
    o[blockIdx.x * 256 + threadIdx.x] = make_float4(0.f, 0.f, 0.f, 0.f);
}

__global__ void __launch_bounds__(128, 1)
ln_stats_kernel(const float* __restrict__ x) {
    int row = blockIdx.x;
    float4 v = reinterpret_cast<const float4*>(x + (size_t)row * D_)[threadIdx.x];
    float s  = v.x + v.y + v.z + v.w;
    float s2 = v.x * v.x + v.y * v.y + v.z * v.z + v.w * v.w;
    #pragma unroll
    for (int off = 16; off > 0; off >>= 1) {
        s  += __shfl_xor_sync(0xffffffffu, s,  off);
        s2 += __shfl_xor_sync(0xffffffffu, s2, off);
    }
    __shared__ float sh[8];
    int w = threadIdx.x >> 5;
    if ((threadIdx.x & 31) == 0) { sh[w] = s; sh[w + 4] = s2; }
    __syncthreads();
    if (threadIdx.x == 0) {
        s  = sh[0] + sh[1] + sh[2] + sh[3];
        s2 = sh[4] + sh[5] + sh[6] + sh[7];
        float mu  = s * (1.0f / D_);
        float var = s2 * (1.0f / D_) - mu * mu;
        g_mu[row] = mu; g_rstd[row] = rsqrtf(var + 1e-5f);
    }
}

// --------------------------- KV projection (FFMA2 inner loop) --------------
#define BM 128
#define BN 128
#define BK 16

__global__ void __launch_bounds__(256, 1)
kvproj_kernel(const float* __restrict__ x, const float* __restrict__ gamma,
              const float* __restrict__ beta, const float* __restrict__ W,
              int half) {
    __shared__ float As[BK][BM];
    __shared__ float Bs[BK][BN];
    int tid = threadIdx.x;
    int tx = tid & 15, ty = tid >> 4;
    int m0 = half * (2 * N_) + blockIdx.y * BM;
    int n0 = D_ + blockIdx.x * BN;

    unsigned long long acc2[8][4];
    #pragma unroll
    for (int i = 0; i < 8; i++)
        #pragma unroll
        for (int jp = 0; jp < 4; jp++) acc2[i][jp] = 0ull;

    for (int kt = 0; kt < D_; kt += BK) {
        #pragma unroll
        for (int i = 0; i < 8; i++) {
            int e = tid + i * 256;
            int m = e >> 4, kk = e & 15;
            int row = m0 + m;
            float xv = x[(size_t)row * D_ + kt + kk];
            xv = (xv - g_mu[row]) * g_rstd[row] * gamma[kt + kk] + beta[kt + kk];
            As[kk][m] = xv;
        }
        #pragma unroll
        for (int i = 0; i < 8; i++) {
            int e = tid + i * 256;
            int kk = e >> 7, n = e & 127;
            Bs[kk][n] = W[(size_t)(kt + kk) * W3_ + n0 + n];
        }
        __syncthreads();
        #pragma unroll
        for (int k = 0; k < BK; k++) {
            float4 a0 = *(const float4*)&As[k][ty * 8];
            float4 a1 = *(const float4*)&As[k][ty * 8 + 4];
            ulonglong2 b01 = *(const ulonglong2*)&Bs[k][tx * 8];
            ulonglong2 b23 = *(const ulonglong2*)&Bs[k][tx * 8 + 4];
            float av[8] = {a0.x, a0.y, a0.z, a0.w, a1.x, a1.y, a1.z, a1.w};
            #pragma unroll
            for (int i = 0; i < 8; i++) {
                unsigned long long aa = bcast2(av[i]);
                ffma2(acc2[i][0], aa, b01.x); ffma2(acc2[i][1], aa, b01.y);
                ffma2(acc2[i][2], aa, b23.x); ffma2(acc2[i][3], aa, b23.y);
            }
        }
        __syncthreads();
    }

    float acc[8][8];
    #pragma unroll
    for (int i = 0; i < 8; i++)
        #pragma unroll
        for (int jp = 0; jp < 4; jp++) {
            F2U u; u.u = acc2[i][jp];
            acc[i][2 * jp] = u.f.x; acc[i][2 * jp + 1] = u.f.y;
        }

    int col_rel = (n0 - D_) + tx * 8;
    int kvsel = col_rel >> 9, within = col_rel & 511;
    int h = within >> 6, d0 = within & 63;
    int r0 = m0 + ty * 8;
    int bb = (r0 >> 11) & 1;            // 8 consecutive rows share bb
    int nb = r0 & (N_ - 1);
    int bbh = bb * H_ + h;
    if (kvsel == 0) {
        #pragma unroll
        for (int i = 0; i < 8; i++) {
            uint32_t hp[4], lp[4];
            #pragma unroll
            for (int jp = 0; jp < 4; jp++)
                split2(acc[i][2 * jp], acc[i][2 * jp + 1], hp[jp], lp[jp]);
            size_t kb = ((size_t)bbh * N_ + nb + i) * DH_ + d0;
            *(uint4*)&g_kh[kb] = make_uint4(hp[0], hp[1], hp[2], hp[3]);
            *(uint4*)&g_kl[kb] = make_uint4(lp[0], lp[1], lp[2], lp[3]);
        }
    } else {
        #pragma unroll
        for (int j = 0; j < 8; j++) {
            uint32_t hp[4], lp[4];
            #pragma unroll
            for (int ip = 0; ip < 4; ip++)
                split2(acc[2 * ip][j], acc[2 * ip + 1][j], hp[ip], lp[ip]);
            size_t vb = ((size_t)bbh * DH_ + d0 + j) * N_ + nb;
            *(uint4*)&g_vh[vb] = make_uint4(hp[0], hp[1], hp[2], hp[3]);
            *(uint4*)&g_vl[vb] = make_uint4(lp[0], lp[1], lp[2], lp[3]);
        }
    }
}

// ---------------------------------------------------------------------------
// Kernel D: fused Q-proj (FFMA2) + tensor-core attention (bf16x3 mma) +
//           tensor-core out-proj (bf16x3 mma via C->A register repack).
// smem layout unchanged from R13 (110592 B, 2 CTAs/SM).
// ---------------------------------------------------------------------------
#define QSTB_   36864
#define BUFB_   36864
#define ATTN_SMEM (QSTB_ + 2 * BUFB_)   // 110592

__global__ void __launch_bounds__(256, 2)
attn_kernel(const float* __restrict__ x, const float* __restrict__ gamma,
            const float* __restrict__ beta, const float* __restrict__ w_qkv,
            const float* __restrict__ w_out, float* __restrict__ out,
            int half) {
    extern __shared__ char smc[];
    float* smf = (float*)smc;
    uint32_t smb = (uint32_t)__cvta_generic_to_shared(smc);

    int tid = threadIdx.x;
    int tx = tid & 7, ty = tid >> 3;          // Q-proj mapping
    int lane = tid & 31;
    int w = tid >> 5;
    int g = lane >> 2, tig = lane & 3;
    int bb = blockIdx.y >> 3, h = blockIdx.y & 7;
    int b  = half * 2 + bb;
    int i0 = blockIdx.x * 128;
    int bbh = bb * H_ + h;

    const unsigned short* kh = g_kh + (size_t)bbh * N_ * DH_;
    const unsigned short* kl = g_kl + (size_t)bbh * N_ * DH_;
    const unsigned short* vh = g_vh + (size_t)bbh * DH_ * N_;
    const unsigned short* vl = g_vl + (size_t)bbh * DH_ * N_;

    // ---- prefetch tile 0 into buffer 0 (group 0) ----
    {
        uint32_t bufb = smb + QSTB_;
        #pragma unroll
        for (int c = 0; c < 2; c++) {
            int cid = tid + c * 256;
            int n = cid >> 3, c8 = (cid & 7) * 8;
            uint32_t so = (uint32_t)(n * 72 + c8) * 2;
            cp16(bufb + so,         kh + (size_t)n * DH_ + c8);
            cp16(bufb + 9216 + so,  kl + (size_t)n * DH_ + c8);
            cp16(bufb + 18432 + so, vh + (size_t)n * N_ + c8);
            cp16(bufb + 27648 + so, vl + (size_t)n * N_ + c8);
        }
        cp_commit();
    }

    // ---- Q-proj: Q[128,64] = LN(x) @ Wq[:,h*64..], FFMA2; staging in buf1 ----
    {
        float* xs = smf + (QSTB_ + BUFB_) / 4;   // [32][132]
        float* Ws = xs + 4224;                   // [32][64]
        unsigned long long qa2[4][4];
        #pragma unroll
        for (int i = 0; i < 4; i++)
            #pragma unroll
            for (int q = 0; q < 4; q++) qa2[i][q] = 0ull;

        for (int kt = 0; kt < D_; kt += 32) {
            #pragma unroll
            for (int it = 0; it < 16; it++) {
                int e = tid + it * 256;
                int i = e >> 5, k = e & 31;
                int row = b * N_ + i0 + i;
                float xv = x[(size_t)row * D_ + kt + k];
                xs[k * 132 + i] = (xv - g_mu[row]) * g_rstd[row] * gamma[kt + k]
                                  + beta[kt + k];
            }
            #pragma unroll
            for (int it = 0; it < 8; it++) {
                int e = tid + it * 256;
                int d = e & 63, k = e >> 6;
                Ws[k * 64 + d] = w_qkv[(size_t)(kt + k) * W3_ + h * DH_ + d];
            }
            __syncthreads();
            #pragma unroll
            for (int k = 0; k < 32; k++) {
                float4 aq = *(const float4*)&xs[k * 132 + ty * 4];
                ulonglong2 bL = *(const ulonglong2*)&Ws[k * 64 + tx * 4];
                ulonglong2 bH = *(const ulonglong2*)&Ws[k * 64 + 32 + tx * 4];
                unsigned long long a0 = bcast2(aq.x), a1 = bcast2(aq.y);
                unsigned long long a2 = bcast2(aq.z), a3 = bcast2(aq.w);
                ffma2(qa2[0][0], a0, bL.x); ffma2(qa2[0][1], a0, bL.y);
                ffma2(qa2[0][2], a0, bH.x); ffma2(qa2[0][3], a0, bH.y);
                ffma2(qa2[1][0], a1, bL.x); ffma2(qa2[1][1], a1, bL.y);
                ffma2(qa2[1][2], a1, bH.x); ffma2(qa2[1][3], a1, bH.y);
                ffma2(qa2[2][0], a2, bL.x); ffma2(qa2[2][1], a2, bL.y);
                ffma2(qa2[2][2], a2, bH.x); ffma2(qa2[2][3], a2, bH.y);
                ffma2(qa2[3][0], a3, bL.x); ffma2(qa2[3][1], a3, bL.y);
                ffma2(qa2[3][2], a3, bH.x); ffma2(qa2[3][3], a3, bH.y);
            }
            __syncthreads();
        }
        // store Q hi/lo bf16 planes [128][72]
        #pragma unroll
        for (int i = 0; i < 4; i++)
            #pragma unroll
            for (int q = 0; q < 4; q++) {
                F2U u; u.u = qa2[i][q];
                int d = ((q >> 1) ? 32 : 0) + tx * 4 + (q & 1) * 2;
                int row = ty * 4 + i;
                uint32_t hp, lp;
                split2(u.f.x, u.f.y, hp, lp);
                *(uint32_t*)(smc + (row * 72 + d) * 2)         = hp;
                *(uint32_t*)(smc + 18432 + (row * 72 + d) * 2) = lp;
            }
    }
    __syncthreads();

    // ---- prefetch tile 1 into buffer 1 (group 1) ----
    {
        uint32_t bufb = smb + QSTB_ + BUFB_;
        #pragma unroll
        for (int c = 0; c < 2; c++) {
            int cid = tid + c * 256;
            int n = cid >> 3, c8 = (cid & 7) * 8;
            uint32_t so = (uint32_t)(n * 72 + c8) * 2;
            cp16(bufb + so,         kh + (size_t)(64 + n) * DH_ + c8);
            cp16(bufb + 9216 + so,  kl + (size_t)(64 + n) * DH_ + c8);
            cp16(bufb + 18432 + so, vh + (size_t)n * N_ + 64 + c8);
            cp16(bufb + 27648 + so, vl + (size_t)n * N_ + 64 + c8);
        }
        cp_commit();
    }

    // ---- load Q fragments (A-frags, m16n8k16) ----
    uint32_t qh[4][4], ql[4][4];
    {
        uint32_t qrow = 16 * w + (lane & 15);
        uint32_t qcol = (lane >> 4) * 8;
        #pragma unroll
        for (int kk = 0; kk < 4; kk++) {
            uint32_t off = (qrow * 72 + 16 * kk + qcol) * 2;
            ldsm4(smb + off,          qh[kk][0], qh[kk][1], qh[kk][2], qh[kk][3]);
            ldsm4(smb + 18432 + off,  ql[kk][0], ql[kk][1], ql[kk][2], ql[kk][3]);
        }
    }

    uint32_t bn = (lane & 7) + ((lane & 16) ? 8 : 0);
    uint32_t bkof = (lane & 8) ? 8 : 0;

    float oc[8][4];
    #pragma unroll
    for (int dt = 0; dt < 8; dt++)
        #pragma unroll
        for (int q = 0; q < 4; q++) oc[dt][q] = 0.f;
    float lpg = 0.f, lpg8 = 0.f;

    for (int t = 0; t < NT_; t++) {
        if (t == NT_ - 1) cp_wait<0>(); else cp_wait<1>();
        __syncthreads();
        uint32_t bufb = smb + QSTB_ + (uint32_t)(t & 1) * BUFB_;
        uint32_t kbh = bufb, kbl = bufb + 9216;
        uint32_t vbh = bufb + 18432, vbl = bufb + 27648;

        #pragma unroll
        for (int hf = 0; hf < 2; hf++) {
            float sc[4][4];
            #pragma unroll
            for (int nt = 0; nt < 4; nt++)
                #pragma unroll
                for (int q = 0; q < 4; q++) sc[nt][q] = 0.f;

            #pragma unroll
            for (int kk = 0; kk < 4; kk++) {
                #pragma unroll
                for (int ap = 0; ap < 2; ap++) {
                    uint32_t koff = ((32 * hf + 16 * ap + bn) * 72 + 16 * kk + bkof) * 2;
                    uint32_t h0, h1, h2, h3, l0, l1, l2, l3;
                    ldsm4(kbh + koff, h0, h1, h2, h3);
                    ldsm4(kbl + koff, l0, l1, l2, l3);
                    int n0t = 2 * ap, n1t = 2 * ap + 1;
                    mma_bf16(sc[n0t][0], sc[n0t][1], sc[n0t][2], sc[n0t][3],
                             qh[kk][0], qh[kk][1], qh[kk][2], qh[kk][3], h0, h1);
                    mma_bf16(sc[n0t][0], sc[n0t][1], sc[n0t][2], sc[n0t][3],
                             qh[kk][0], qh[kk][1], qh[kk][2], qh[kk][3], l0, l1);
                    mma_bf16(sc[n0t][0], sc[n0t][1], sc[n0t][2], sc[n0t][3],
                             ql[kk][0], ql[kk][1], ql[kk][2], ql[kk][3], h0, h1);
                    mma_bf16(sc[n1t][0], sc[n1t][1], sc[n1t][2], sc[n1t][3],
                             qh[kk][0], qh[kk][1], qh[kk][2], qh[kk][3], h2, h3);
                    mma_bf16(sc[n1t][0], sc[n1t][1], sc[n1t][2], sc[n1t][3],
                             qh[kk][0], qh[kk][1], qh[kk][2], qh[kk][3], l2, l3);
                    mma_bf16(sc[n1t][0], sc[n1t][1], sc[n1t][2], sc[n1t][3],
                             ql[kk][0], ql[kk][1], ql[kk][2], ql[kk][3], h2, h3);
                }
            }

            #pragma unroll
            for (int k2 = 0; k2 < 2; k2++) {
                uint32_t pa_h[4], pa_l[4];
                #pragma unroll
                for (int e = 0; e < 2; e++) {
                    int nt = 2 * k2 + e;
                    float p0 = ex2(sc[nt][0] * KEXP_);
                    float p1 = ex2(sc[nt][1] * KEXP_);
                    float p2 = ex2(sc[nt][2] * KEXP_);
                    float p3 = ex2(sc[nt][3] * KEXP_);
                    lpg  += p0 + p1;
                    lpg8 += p2 + p3;
                    uint32_t h01, l01, h23, l23;
                    split2(p0, p1, h01, l01);
                    split2(p2, p3, h23, l23);
                    pa_h[2 * e] = h01; pa_h[2 * e + 1] = h23;
                    pa_l[2 * e] = l01; pa_l[2 * e + 1] = l23;
                }
                #pragma unroll
                for (int a = 0; a < 4; a++) {
                    uint32_t voff = ((16 * a + bn) * 72 + 32 * hf + 16 * k2 + bkof) * 2;
                    uint32_t h0, h1, h2, h3, l0, l1, l2, l3;
                    ldsm4(vbh + voff, h0, h1, h2, h3);
                    ldsm4(vbl + voff, l0, l1, l2, l3);
                    int d0t = 2 * a, d1t = 2 * a + 1;
                    mma_bf16(oc[d0t][0], oc[d0t][1], oc[d0t][2], oc[d0t][3],
                             pa_h[0], pa_h[1], pa_h[2], pa_h[3], h0, h1);
                    mma_bf16(oc[d0t][0], oc[d0t][1], oc[d0t][2], oc[d0t][3],
                             pa_h[0], pa_h[1], pa_h[2], pa_h[3], l0, l1);
                    mma_bf16(oc[d0t][0], oc[d0t][1], oc[d0t][2], oc[d0t][3],
                             pa_l[0], pa_l[1], pa_l[2], pa_l[3], h0, h1);
                    mma_bf16(oc[d1t][0], oc[d1t][1], oc[d1t][2], oc[d1t][3],
                             pa_h[0], pa_h[1], pa_h[2], pa_h[3], h2, h3);
                    mma_bf16(oc[d1t][0], oc[d1t][1], oc[d1t][2], oc[d1t][3],
                             pa_h[0], pa_h[1], pa_h[2], pa_h[3], l2, l3);
                    mma_bf16(oc[d1t][0], oc[d1t][1], oc[d1t][2], oc[d1t][3],
                             pa_l[0], pa_l[1], pa_l[2], pa_l[3], h2, h3);
                }
            }
        }
        __syncthreads();

        if (t + 2 < NT_) {
            int j0n = (t + 2) * 64;
            #pragma unroll
            for (int c = 0; c < 2; c++) {
                int cid = tid + c * 256;
                int n = cid >> 3, c8 = (cid & 7) * 8;
                uint32_t so = (uint32_t)(n * 72 + c8) * 2;
                cp16(bufb + so,         kh + (size_t)(j0n + n) * DH_ + c8);
                cp16(bufb + 9216 + so,  kl + (size_t)(j0n + n) * DH_ + c8);
                cp16(bufb + 18432 + so, vh + (size_t)n * N_ + j0n + c8);
                cp16(bufb + 27648 + so, vl + (size_t)n * N_ + j0n + c8);
            }
            cp_commit();
        }
    }

    // ---- finalize l (reduce over the 4 lanes of each quad) ----
    lpg  += __shfl_xor_sync(0xffffffffu, lpg, 1);
    lpg  += __shfl_xor_sync(0xffffffffu, lpg, 2);
    lpg8 += __shfl_xor_sync(0xffffffffu, lpg8, 1);
    lpg8 += __shfl_xor_sync(0xffffffffu, lpg8, 2);
    float invg = 1.0f / lpg, invg8 = 1.0f / lpg8;

    // ---- build ao A-frags directly from PV C-frags (proven repack) ----
    // A-frag (m16k16) reg r: r0=(row g, k=2tig), r1=(row g+8, k), r2=(row g,
    // k+8), r3=(row g+8, k+8). oc[dt] C-frag: c0,c1=(row g, d=8dt+2tig,+1),
    // c2,c3=(row g+8). k-step kk covers d=16kk..+15 -> dt=2kk (k), 2kk+1 (k+8).
    uint32_t ah[4][4], al[4][4];
    #pragma unroll
    for (int kk = 0; kk < 4; kk++) {
        split2(oc[2 * kk][0] * invg,      oc[2 * kk][1] * invg,      ah[kk][0], al[kk][0]);
        split2(oc[2 * kk][2] * invg8,     oc[2 * kk][3] * invg8,     ah[kk][1], al[kk][1]);
        split2(oc[2 * kk + 1][0] * invg,  oc[2 * kk + 1][1] * invg,  ah[kk][2], al[kk][2]);
        split2(oc[2 * kk + 1][2] * invg8, oc[2 * kk + 1][3] * invg8, ah[kk][3], al[kk][3]);
    }

    // ---- out-proj: out += ao @ Wout[h*64..+63, :], tensor bf16x3 ----
    // Stage WoT[n][d] hi/lo bf16, pitch 72, in buffer0 region.
    uint32_t wth = smb + QSTB_;
    uint32_t wtl = wth + 9216;
    int row0 = b * N_ + i0 + 16 * w + g;

    for (int nt = 0; nt < D_; nt += 64) {
        __syncthreads();   // prior iter's ldsm reads done
        #pragma unroll
        for (int it = 0; it < 8; it++) {
            int e = tid + it * 256;
            int n = e >> 5, d2 = (e & 31) * 2;
            float v0 = w_out[(size_t)(h * DH_ + d2) * D_ + nt + n];
            float v1 = w_out[(size_t)(h * DH_ + d2 + 1) * D_ + nt + n];
            uint32_t hp, lp; split2(v0, v1, hp, lp);
            *(uint32_t*)(smc + QSTB_ + (n * 72 + d2) * 2)        = hp;
            *(uint32_t*)(smc + QSTB_ + 9216 + (n * 72 + d2) * 2) = lp;
        }
        __syncthreads();

        float oc2[8][4];
        #pragma unroll
        for (int s = 0; s < 8; s++)
            #pragma unroll
            for (int q = 0; q < 4; q++) oc2[s][q] = 0.f;

        #pragma unroll
        for (int np = 0; np < 4; np++) {
            #pragma unroll
            for (int kk = 0; kk < 4; kk++) {
                uint32_t off = ((16 * np + bn) * 72 + 16 * kk + bkof) * 2;
                uint32_t h0, h1, h2, h3, l0, l1, l2, l3;
                ldsm4(wth + off, h0, h1, h2, h3);
                ldsm4(wtl + off, l0, l1, l2, l3);
                int s0 = 2 * np, s1 = 2 * np + 1;
                mma_bf16(oc2[s0][0], oc2[s0][1], oc2[s0][2], oc2[s0][3],
                         ah[kk][0], ah[kk][1], ah[kk][2], ah[kk][3], h0, h1);
                mma_bf16(oc2[s0][0], oc2[s0][1], oc2[s0][2], oc2[s0][3],
                         ah[kk][0], ah[kk][1], ah[kk][2], ah[kk][3], l0, l1);
                mma_bf16(oc2[s0][0], oc2[s0][1], oc2[s0][2], oc2[s0][3],
                         al[kk][0], al[kk][1], al[kk][2], al[kk][3], h0, h1);
                mma_bf16(oc2[s1][0], oc2[s1][1], oc2[s1][2], oc2[s1][3],
                         ah[kk][0], ah[kk][1], ah[kk][2], ah[kk][3], h2, h3);
                mma_bf16(oc2[s1][0], oc2[s1][1], oc2[s1][2], oc2[s1][3],
                         ah[kk][0], ah[kk][1], ah[kk][2], ah[kk][3], l2, l3);
                mma_bf16(oc2[s1][0], oc2[s1][1], oc2[s1][2], oc2[s1][3],
                         al[kk][0], al[kk][1], al[kk][2], al[kk][3], h2, h3);
            }
        }

        #pragma unroll
        for (int s = 0; s < 8; s++) {
            int nc = nt + 8 * s + 2 * tig;
            atomicAdd(&out[(size_t)row0 * D_ + nc],           oc2[s][0]);
            atomicAdd(&out[(size_t)row0 * D_ + nc + 1],       oc2[s][1]);
            atomicAdd(&out[(size_t)(row0 + 8) * D_ + nc],     oc2[s][2]);
            atomicAdd(&out[(size_t)(row0 + 8) * D_ + nc + 1], oc2[s][3]);
        }
    }
}

// ---------------------------------------------------------------------------
extern "C" void kernel_launch(void* const* d_in, const int* in_sizes, int n_in,
                              void* d_out, int out_size) {
    const float* x     = (const float*)d_in[0];
    const float* gamma = (const float*)d_in[1];
    const float* beta  = (const float*)d_in[2];
    const float* w_qkv = (const float*)d_in[3];
    const float* w_out = (const float*)d_in[4];
    float* out = (float*)d_out;
    (void)in_sizes; (void)n_in; (void)out_size;

    cudaFuncSetAttribute(attn_kernel,
                         cudaFuncAttributeMaxDynamicSharedMemorySize,
                         ATTN_SMEM);

    zero_out_kernel<<<ROWS_ * D_ / 1024, 256>>>((float4*)out);
    ln_stats_kernel<<<ROWS_, 128>>>(x);

    for (int half = 0; half < 2; half++) {
        kvproj_kernel<<<dim3(2 * D_ / BN, 2 * N_ / BM), 256>>>(
            x, gamma, beta, w_qkv, half);
        attn_kernel<<<dim3(N_ / 128, 2 * H_), 256, ATTN_SMEM>>>(
            x, gamma, beta, w_qkv, w_out, out, half);
    }
}